// round 6
// baseline (speedup 1.0000x reference)
#include <cuda_runtime.h>
#include <math.h>
#define FULL 0xffffffffu
typedef unsigned long long u64;

__device__ float g_M1T[128*128];              // M1 transposed: [c][e]
__device__ float g_qstate[32*16*128];
__device__ float g_qkg[32*16*128];
__device__ float g_cq1[32*16];
__device__ float g_cq0[32*16];
__device__ float g_Tpart[32*16*16*128];
__device__ float g_t1p[32*16*16];
__device__ float g_t2p[32*16*16];
__device__ float g_rstd[32*4096];
__device__ float g_m[32*4096];

static __device__ __forceinline__ float dot4(float4 a, float4 b) {
    return fmaf(a.x,b.x,fmaf(a.y,b.y,fmaf(a.z,b.z,a.w*b.w)));
}
static __device__ __forceinline__ u64 ffma2(u64 a,u64 b,u64 c){
    u64 d; asm("fma.rn.f32x2 %0,%1,%2,%3;":"=l"(d):"l"(a),"l"(b),"l"(c)); return d;
}
static __device__ __forceinline__ u64 fmul2(u64 a,u64 b){
    u64 d; asm("mul.rn.f32x2 %0,%1,%2;":"=l"(d):"l"(a),"l"(b)); return d;
}
static __device__ __forceinline__ u64 pack2(float lo,float hi){
    u64 d; asm("mov.b64 %0,{%1,%2};":"=l"(d):"f"(lo),"f"(hi)); return d;
}
static __device__ __forceinline__ float2 unpack2(u64 v){
    float lo,hi; asm("mov.b64 {%0,%1},%2;":"=f"(lo),"=f"(hi):"l"(v));
    return make_float2(lo,hi);
}
static __device__ __forceinline__ float hsum2(u64 v){
    float2 a=unpack2(v); return a.x+a.y;
}
static __device__ __forceinline__ float butterfly16(const float* v, int l) {
    float u8[8];
    { bool hi=(l&16);
#pragma unroll
      for(int j=0;j<8;j++){float mi=hi?v[j+8]:v[j],ot=hi?v[j]:v[j+8];
        u8[j]=mi+__shfl_xor_sync(FULL,ot,16);} }
    float u4[4];
    { bool hi=(l&8);
#pragma unroll
      for(int j=0;j<4;j++){float mi=hi?u8[j+4]:u8[j],ot=hi?u8[j]:u8[j+4];
        u4[j]=mi+__shfl_xor_sync(FULL,ot,8);} }
    float u2[2];
    { bool hi=(l&4);
#pragma unroll
      for(int j=0;j<2;j++){float mi=hi?u4[j+2]:u4[j],ot=hi?u4[j]:u4[j+2];
        u2[j]=mi+__shfl_xor_sync(FULL,ot,4);} }
    float u1;
    { bool hi=(l&2);
      float mi=hi?u2[1]:u2[0],ot=hi?u2[0]:u2[1];
      u1=mi+__shfl_xor_sync(FULL,ot,2); }
    return u1+__shfl_xor_sync(FULL,u1,1);
}
static __device__ __forceinline__ float fexp(float x) {
    x = fmaxf(x, -87.f);
    float t = fmaf(x, 1.4426950408889634f, 12582912.f);
    int ni = __float_as_int(t) - 0x4B400000;
    float n = t - 12582912.f;
    float f = fmaf(x, 1.4426950408889634f, -n);
    float p = 1.5403530e-4f;
    p = fmaf(p,f,1.3333558e-3f); p = fmaf(p,f,9.6181291e-3f);
    p = fmaf(p,f,5.5504109e-2f); p = fmaf(p,f,2.4022651e-1f);
    p = fmaf(p,f,6.9314718e-1f); p = fmaf(p,f,1.f);
    return p * __int_as_float((ni + 127) << 23);
}

__global__ void kcopy(const float* __restrict__ s){
    int i = blockIdx.x*128+threadIdx.x; g_qstate[i]=s[i];
}
__global__ void kM1(const float* __restrict__ Wq, const float* __restrict__ Wk){
    int e=blockIdx.x, d=threadIdx.x; float a=0.f;
    for(int c=0;c<128;c++) a=fmaf(Wq[c*128+e],Wk[c*128+d],a);
    g_M1T[d*128+e]=a*0.08838834764831845f;   // transposed store
}

static __device__ __forceinline__ void ln_rows8(const float (*sq)[128], float (*sz)[128],
        const float* gq, const float* bq, int w, int l){
    float4 y4=((const float4*)sq[w])[l];
    float s=y4.x+y4.y+y4.z+y4.w;
    float s2=fmaf(y4.x,y4.x,fmaf(y4.y,y4.y,fmaf(y4.z,y4.z,y4.w*y4.w)));
#pragma unroll
    for(int d=16;d>0;d>>=1){s+=__shfl_xor_sync(FULL,s,d);s2+=__shfl_xor_sync(FULL,s2,d);}
    float m=s*(1.f/128.f);
    float rstd=rsqrtf(fmaf(s2,1.f/128.f,-m*m)+1e-5f);
    float4 gg=((const float4*)gq)[l], bb=((const float4*)bq)[l];
    float4 z4;
    z4.x=fmaf((y4.x-m)*rstd,gg.x,bb.x); z4.y=fmaf((y4.y-m)*rstd,gg.y,bb.y);
    z4.z=fmaf((y4.z-m)*rstd,gg.z,bb.z); z4.w=fmaf((y4.w-m)*rstd,gg.w,bb.w);
    ((float4*)sz[w])[l]=z4;
}

// qk projection (f32x2, M1T) for 8 rows in sz -> qkraw, then qkg/cq. 512 thr.
static __device__ __forceinline__ void qkproj512(const float (*sz)[128], float (*qkraw)[128],
        const float* gkv, const float* bkv, int qbase, int t, int w, int l){
    int c=t&127, rq=(t>>7)*2;
    u64 a0=0ull,a1=0ull;
    const ulonglong2* mt=(const ulonglong2*)(g_M1T+(size_t)c*128);
#pragma unroll 8
    for(int d=0;d<32;d++){
        ulonglong2 mv=mt[d];
        ulonglong2 z0=((const ulonglong2*)sz[rq])[d];
        ulonglong2 z1=((const ulonglong2*)sz[rq+1])[d];
        a0=ffma2(z0.x,mv.x,a0); a0=ffma2(z0.y,mv.y,a0);
        a1=ffma2(z1.x,mv.x,a1); a1=ffma2(z1.y,mv.y,a1);
    }
    qkraw[rq][c]=hsum2(a0); qkraw[rq+1][c]=hsum2(a1);
    __syncthreads();
    if(w<8){
        float4 qr=((const float4*)qkraw[w])[l];
        float4 g4=((const float4*)gkv)[l], b4=((const float4*)bkv)[l];
        float c1=dot4(qr,g4), c0=dot4(qr,b4);
#pragma unroll
        for(int d=16;d>0;d>>=1){c1+=__shfl_xor_sync(FULL,c1,d);c0+=__shfl_xor_sync(FULL,c0,d);}
        if(l==0){g_cq1[qbase+w]=c1; g_cq0[qbase+w]=c0;}
        float4 o; o.x=qr.x*g4.x; o.y=qr.y*g4.y; o.z=qr.z*g4.z; o.w=qr.w*g4.w;
        ((float4*)(g_qkg+(qbase+w)*128))[l]=o;
    }
}

__global__ void __launch_bounds__(512) kqk0(const float* __restrict__ gq,
        const float* __restrict__ bq, const float* __restrict__ gkv,
        const float* __restrict__ bkv){
    int qbase=blockIdx.x*8, t=threadIdx.x, w=t>>5, l=t&31;
    __shared__ float sq[8][128], sz[8][128], qkraw[8][128];
#pragma unroll
    for(int k=0;k<2;k++) ((float*)sq)[k*512+t]=g_qstate[qbase*128+k*512+t];
    __syncthreads();
    if(w<8) ln_rows8(sq,sz,gq,bq,w,l);
    __syncthreads();
    qkproj512(sz,qkraw,gkv,bkv,qbase,t,w,l);
}

// ---- stream: grid(16,32), 256 thr, 256 rows/block ----
__global__ void __launch_bounds__(256,2) kstream4(const float* __restrict__ inp,
        float* __restrict__ a0out, int writeA0, int iter0){
    __shared__ float dbuf[256*17];
    __shared__ float rstd_s[256], m_s[256];
    __shared__ ulonglong2 qks[16][32];     // phase3 reuse as Sblk[2048]
    __shared__ float t1s[16], t2s[16];
    float* Sblk=(float*)qks;
    int p=blockIdx.x, b=blockIdx.y, t=threadIdx.x, w=t>>5, l=t&31;
    if(t<16){t1s[t]=0.f;t2s[t]=0.f;}
#pragma unroll
    for(int k=0;k<2;k++)
        ((ulonglong2*)qks)[k*256+t]=((const ulonglong2*)(g_qkg+b*2048))[k*256+t];
    if(!iter0){
        rstd_s[t]=g_rstd[b*4096+p*256+t];
        m_s[t]=g_m[b*4096+p*256+t];
    }
    __syncthreads();
    int rb=w*32;
    const ulonglong2* base=(const ulonglong2*)(inp+((size_t)b*4096+p*256+rb)*128);
    // phase 1: dots (+ LN stats if iter0) -> logits
    {
        float cq1v=g_cq1[b*16+(l>>1)], cq0v=g_cq0[b*16+(l>>1)];
        for(int i=0;i<32;i++){
            ulonglong2 xp=base[i*32+l];
            float v[16];
#pragma unroll
            for(int q=0;q<16;q++){
                ulonglong2 qq=qks[q][l];
                v[q]=hsum2(ffma2(xp.y,qq.y,fmul2(xp.x,qq.x)));
            }
            int row=rb+i;
            float rs,m;
            if(iter0){
                float2 x01=unpack2(xp.x), x23=unpack2(xp.y);
                float s=(x01.x+x01.y)+(x23.x+x23.y);
                float s2=fmaf(x01.x,x01.x,fmaf(x01.y,x01.y,
                          fmaf(x23.x,x23.x,x23.y*x23.y)));
#pragma unroll
                for(int d=16;d>0;d>>=1){s+=__shfl_xor_sync(FULL,s,d);s2+=__shfl_xor_sync(FULL,s2,d);}
                m=s*(1.f/128.f);
                rs=rsqrtf(fmaf(s2,1.f/128.f,-m*m)+1e-5f);
                if(l==0){rstd_s[row]=rs;m_s[row]=m;}
            }
            float u1=butterfly16(v,l);
            if((l&1)==0){
                if(!iter0){ rs=rstd_s[row]; m=m_s[row]; }
                dbuf[row*17+(l>>1)]=fmaf(rs,fmaf(-m,cq1v,u1),cq0v);
            }
        }
    }
    __syncthreads();
    if(iter0){
        g_rstd[b*4096+p*256+t]=rstd_s[t];
        g_m[b*4096+p*256+t]=m_s[t];
    }
    // phase 2: softmax per row (thread=row)
    {
        int r=t;
        float rs=rstd_s[r], mv=m_s[r];
        float a0[16], mx=-1e30f;
#pragma unroll
        for(int q=0;q<16;q++){a0[q]=dbuf[r*17+q]; mx=fmaxf(mx,a0[q]);}
        float ssum=0.f;
#pragma unroll
        for(int q=0;q<16;q++){a0[q]=fexp(a0[q]-mx); ssum+=a0[q];}
        float inv=1.f/ssum;
        float t1v[16];
#pragma unroll
        for(int q=0;q<16;q++){
            a0[q]*=inv;
            dbuf[r*17+q]=a0[q]*rs;
            t1v[q]=a0[q]*rs*mv;
        }
        float t2r=butterfly16(a0,l), t1r=butterfly16(t1v,l);
        if((l&1)==0){atomicAdd(&t2s[l>>1],t2r);atomicAdd(&t1s[l>>1],t1r);}
        if(writeA0){
            float* dst=a0out+(size_t)b*65536+p*256+t;
#pragma unroll
            for(int q=0;q<16;q++) dst[(size_t)q*4096]=a0[q];
        }
    }
    __syncthreads();
    // phase 3: S += w*x (f32x2)
    {
        u64 Sa[16],Sb[16];
#pragma unroll
        for(int q=0;q<16;q++){Sa[q]=0ull;Sb[q]=0ull;}
        const float* wb=dbuf+rb*17;
        for(int i=0;i<32;i++){
            ulonglong2 xp=base[i*32+l];
            const float* wr=wb+i*17;
#pragma unroll
            for(int q=0;q<16;q++){
                u64 w2=pack2(wr[q],wr[q]);
                Sa[q]=ffma2(w2,xp.x,Sa[q]);
                Sb[q]=ffma2(w2,xp.y,Sb[q]);
            }
        }
        __syncthreads();
        for(int i=t;i<2048;i+=256) Sblk[i]=0.f;
        __syncthreads();
#pragma unroll
        for(int q=0;q<16;q++){
            float2 a=unpack2(Sa[q]), c=unpack2(Sb[q]);
            atomicAdd(&Sblk[q*128+4*l+0],a.x);
            atomicAdd(&Sblk[q*128+4*l+1],a.y);
            atomicAdd(&Sblk[q*128+4*l+2],c.x);
            atomicAdd(&Sblk[q*128+4*l+3],c.y);
        }
    }
    __syncthreads();
    float* tp=g_Tpart+((size_t)(b*16+p))*2048;
    for(int i=t;i<2048;i+=256) tp[i]=Sblk[i];
    if(t<16){g_t1p[(b*16+p)*16+t]=t1s[t];g_t2p[(b*16+p)*16+t]=t2s[t];}
}

// ---- fused tail, 64 blocks x 512 thr, f32x2 everywhere ----
__global__ void __launch_bounds__(512) ktail(const float* __restrict__ Wv,
        const float* __restrict__ gkv, const float* __restrict__ bkv,
        const float* __restrict__ wih, const float* __restrict__ whh,
        const float* __restrict__ bih, const float* __restrict__ bhh,
        const float* __restrict__ g2, const float* __restrict__ b2ln,
        const float* __restrict__ w1, const float* __restrict__ b1,
        const float* __restrict__ w2, const float* __restrict__ b2f,
        const float* __restrict__ gq, const float* __restrict__ bq,
        float* __restrict__ qout, int last){
    int blk=blockIdx.x, b=blk>>1, qh=(blk&1)*8;
    int t=threadIdx.x, w=t>>5, l=t&31;
    __shared__ float Sh[8][128], su[8][128], sx[8][128], sy[8][128], sh1[8][512];
    __shared__ float t1a[8], t2a[8], rsa[8];
    if(t<8){
        float s1=0.f,s2=0.f;
        for(int p=0;p<16;p++){
            s1+=g_t1p[(b*16+p)*16+qh+t];
            s2+=g_t2p[(b*16+p)*16+qh+t];
        }
        t1a[t]=s1; t2a[t]=s2; rsa[t]=1.f/(s2+1e-5f);
    }
#pragma unroll
    for(int k=0;k<2;k++)
        ((float*)sx)[k*512+t]=g_qstate[(b*16+qh)*128+k*512+t];
    __syncthreads();
    // S reduce + kv-LN correction
#pragma unroll
    for(int k=0;k<2;k++){
        int idx=k*512+t, q=idx>>7, c=idx&127;
        float a=0.f;
        for(int p=0;p<16;p++) a+=g_Tpart[((size_t)(b*16+p))*2048+(qh+q)*128+c];
        ((float*)Sh)[idx]=fmaf(gkv[c],a-t1a[q],bkv[c]*t2a[q]);
    }
    __syncthreads();
    // u = Sh @ Wv^T * rs
    {
        int c=t&127, qg=(t>>7)*2;
        u64 a0=0ull,a1=0ull;
        const ulonglong2* wr=(const ulonglong2*)(Wv+(size_t)c*128);
#pragma unroll 8
        for(int d=0;d<32;d++){
            ulonglong2 wv=wr[d];
            ulonglong2 s0=((const ulonglong2*)Sh[qg])[d];
            ulonglong2 s1=((const ulonglong2*)Sh[qg+1])[d];
            a0=ffma2(s0.x,wv.x,a0); a0=ffma2(s0.y,wv.y,a0);
            a1=ffma2(s1.x,wv.x,a1); a1=ffma2(s1.y,wv.y,a1);
        }
        su[qg][c]=hsum2(a0)*rsa[qg];
        su[qg+1][c]=hsum2(a1)*rsa[qg+1];
    }
    __syncthreads();
    // GRU -> sy
    {
        int c=t&127, rh=(t>>7)*2;
        u64 IR[2]={0,0},IZ[2]={0,0},IN_[2]={0,0},HR[2]={0,0},HZ[2]={0,0},HN[2]={0,0};
        const ulonglong2* wir=(const ulonglong2*)(wih+(size_t)c*128);
        const ulonglong2* wiz=(const ulonglong2*)(wih+(size_t)(c+128)*128);
        const ulonglong2* win=(const ulonglong2*)(wih+(size_t)(c+256)*128);
        const ulonglong2* whr=(const ulonglong2*)(whh+(size_t)c*128);
        const ulonglong2* whz=(const ulonglong2*)(whh+(size_t)(c+128)*128);
        const ulonglong2* whn=(const ulonglong2*)(whh+(size_t)(c+256)*128);
#pragma unroll 4
        for(int d=0;d<32;d++){
            ulonglong2 w0=wir[d],w1_=wiz[d],w2_=win[d],w3=whr[d],w4=whz[d],w5=whn[d];
#pragma unroll
            for(int k=0;k<2;k++){
                ulonglong2 u4=((const ulonglong2*)su[rh+k])[d];
                ulonglong2 x4=((const ulonglong2*)sx[rh+k])[d];
                IR[k]=ffma2(u4.x,w0.x,IR[k]);  IR[k]=ffma2(u4.y,w0.y,IR[k]);
                IZ[k]=ffma2(u4.x,w1_.x,IZ[k]); IZ[k]=ffma2(u4.y,w1_.y,IZ[k]);
                IN_[k]=ffma2(u4.x,w2_.x,IN_[k]);IN_[k]=ffma2(u4.y,w2_.y,IN_[k]);
                HR[k]=ffma2(x4.x,w3.x,HR[k]);  HR[k]=ffma2(x4.y,w3.y,HR[k]);
                HZ[k]=ffma2(x4.x,w4.x,HZ[k]);  HZ[k]=ffma2(x4.y,w4.y,HZ[k]);
                HN[k]=ffma2(x4.x,w5.x,HN[k]);  HN[k]=ffma2(x4.y,w5.y,HN[k]);
            }
        }
        float bir=bih[c],biz=bih[c+128],bin=bih[c+256];
        float bhr=bhh[c],bhz=bhh[c+128],bhn=bhh[c+256];
#pragma unroll
        for(int k=0;k<2;k++){
            float rr=1.f/(1.f+fexp(-(hsum2(IR[k])+bir+hsum2(HR[k])+bhr)));
            float zz=1.f/(1.f+fexp(-(hsum2(IZ[k])+biz+hsum2(HZ[k])+bhz)));
            float nn=tanhf(hsum2(IN_[k])+bin+rr*(hsum2(HN[k])+bhn));
            sy[rh+k][c]=(1.f-zz)*nn+zz*sx[rh+k][c];
        }
    }
    __syncthreads();
    if(w<8) ln_rows8(sy,Sh,g2,b2ln,w,l);
    __syncthreads();
    // FFN1: one output per thread
    {
        u64 acc[8]={0ull,0ull,0ull,0ull,0ull,0ull,0ull,0ull};
        const ulonglong2* wa=(const ulonglong2*)(w1+(size_t)t*128);
#pragma unroll 4
        for(int d=0;d<32;d++){
            ulonglong2 a=wa[d];
#pragma unroll
            for(int r=0;r<8;r++){
                ulonglong2 zz=((const ulonglong2*)Sh[r])[d];
                acc[r]=ffma2(zz.x,a.x,acc[r]);
                acc[r]=ffma2(zz.y,a.y,acc[r]);
            }
        }
        float bb=b1[t];
#pragma unroll
        for(int r=0;r<8;r++) sh1[r][t]=fmaxf(hsum2(acc[r])+bb,0.f);
    }
    __syncthreads();
    // FFN2 + residual
    {
        int c=t&127, rh=(t>>7)*2;
        u64 a0=0ull,a1=0ull;
        const ulonglong2* wp=(const ulonglong2*)(w2+(size_t)c*512);
#pragma unroll 8
        for(int d=0;d<128;d++){
            ulonglong2 wv=wp[d];
            ulonglong2 h0=((const ulonglong2*)sh1[rh])[d];
            ulonglong2 h1=((const ulonglong2*)sh1[rh+1])[d];
            a0=ffma2(h0.x,wv.x,a0); a0=ffma2(h0.y,wv.y,a0);
            a1=ffma2(h1.x,wv.x,a1); a1=ffma2(h1.y,wv.y,a1);
        }
        float bb=b2f[c];
        float v0=sy[rh][c]+hsum2(a0)+bb;
        float v1=sy[rh+1][c]+hsum2(a1)+bb;
        g_qstate[(b*16+qh+rh)*128+c]=v0;
        g_qstate[(b*16+qh+rh+1)*128+c]=v1;
        su[rh][c]=v0; su[rh+1][c]=v1;
        if(last){
            qout[(b*16+qh+rh)*128+c]=v0;
            qout[(b*16+qh+rh+1)*128+c]=v1;
        }
    }
    __syncthreads();
    if(last) return;
    if(w<8) ln_rows8(su,sy,gq,bq,w,l);
    __syncthreads();
    qkproj512(sy,Sh,gkv,bkv,b*16+qh,t,w,l);
}

extern "C" void kernel_launch(void* const* d_in, const int* in_sizes, int n_in,
                              void* d_out, int out_size){
    const float* inp=(const float*)d_in[0];
    const float* query=(const float*)d_in[1];
    const float* ln_kv_g=(const float*)d_in[2];
    const float* ln_kv_b=(const float*)d_in[3];
    const float* Wk=(const float*)d_in[4];
    const float* Wv=(const float*)d_in[5];
    const float* ln_q_g=(const float*)d_in[6];
    const float* ln_q_b=(const float*)d_in[7];
    const float* Wq=(const float*)d_in[8];
    const float* gru_wih=(const float*)d_in[9];
    const float* gru_whh=(const float*)d_in[10];
    const float* gru_bih=(const float*)d_in[11];
    const float* gru_bhh=(const float*)d_in[12];
    const float* ln2_g=(const float*)d_in[13];
    const float* ln2_b=(const float*)d_in[14];
    const float* ffn_w1=(const float*)d_in[15];
    const float* ffn_b1=(const float*)d_in[16];
    const float* ffn_w2=(const float*)d_in[17];
    const float* ffn_b2=(const float*)d_in[18];
    float* out=(float*)d_out;
    float* a0out=out+32*16*128;

    kM1<<<128,128>>>(Wq,Wk);
    kcopy<<<512,128>>>(query);
    kqk0<<<64,512>>>(ln_q_g,ln_q_b,ln_kv_g,ln_kv_b);
    for(int it=0;it<3;it++){
        int last=(it==2);
        kstream4<<<dim3(16,32),256>>>(inp,a0out,last,it==0);
        ktail<<<64,512>>>(Wv,ln_kv_g,ln_kv_b,gru_wih,gru_whh,gru_bih,gru_bhh,
                          ln2_g,ln2_b,ffn_w1,ffn_b1,ffn_w2,ffn_b2,
                          ln_q_g,ln_q_b,out,last);
    }
}

// round 7
// speedup vs baseline: 1.4644x; 1.4644x over previous
#include <cuda_runtime.h>
#include <math.h>
#define FULL 0xffffffffu

__device__ float g_M1[128*128];
__device__ float g_qstate[32*16*128];
__device__ float g_qkg[32*16*128];
__device__ float g_cq1[32*16];
__device__ float g_cq0[32*16];
__device__ float g_Tpart[32*8*16*128];
__device__ float g_t1p[32*8*16];
__device__ float g_t2p[32*8*16];
__device__ float g_rstdc[32*4096];
__device__ float g_mc[32*4096];

static __device__ __forceinline__ float dot4(float4 a, float4 b) {
    return fmaf(a.x,b.x,fmaf(a.y,b.y,fmaf(a.z,b.z,a.w*b.w)));
}
static __device__ __forceinline__ float butterfly16(const float* v, int l) {
    float u8[8];
    { bool hi=(l&16);
#pragma unroll
      for(int j=0;j<8;j++){float mi=hi?v[j+8]:v[j],ot=hi?v[j]:v[j+8];
        u8[j]=mi+__shfl_xor_sync(FULL,ot,16);} }
    float u4[4];
    { bool hi=(l&8);
#pragma unroll
      for(int j=0;j<4;j++){float mi=hi?u8[j+4]:u8[j],ot=hi?u8[j]:u8[j+4];
        u4[j]=mi+__shfl_xor_sync(FULL,ot,8);} }
    float u2[2];
    { bool hi=(l&4);
#pragma unroll
      for(int j=0;j<2;j++){float mi=hi?u4[j+2]:u4[j],ot=hi?u4[j]:u4[j+2];
        u2[j]=mi+__shfl_xor_sync(FULL,ot,4);} }
    float u1;
    { bool hi=(l&2);
      float mi=hi?u2[1]:u2[0],ot=hi?u2[0]:u2[1];
      u1=mi+__shfl_xor_sync(FULL,ot,2); }
    return u1+__shfl_xor_sync(FULL,u1,1);
}
static __device__ __forceinline__ float fexp(float x) {
    x = fmaxf(x, -87.f);
    float t = fmaf(x, 1.4426950408889634f, 12582912.f);
    int ni = __float_as_int(t) - 0x4B400000;
    float n = t - 12582912.f;
    float f = fmaf(x, 1.4426950408889634f, -n);
    float p = 1.5403530e-4f;
    p = fmaf(p,f,1.3333558e-3f); p = fmaf(p,f,9.6181291e-3f);
    p = fmaf(p,f,5.5504109e-2f); p = fmaf(p,f,2.4022651e-1f);
    p = fmaf(p,f,6.9314718e-1f); p = fmaf(p,f,1.f);
    return p * __int_as_float((ni + 127) << 23);
}

__global__ void kcopy(const float* __restrict__ s){
    int i = blockIdx.x*128+threadIdx.x; g_qstate[i]=s[i];
}
__global__ void kM1(const float* __restrict__ Wq, const float* __restrict__ Wk){
    int e=blockIdx.x, d=threadIdx.x; float a=0.f;
    for(int c=0;c<128;c++) a=fmaf(Wq[c*128+e],Wk[c*128+d],a);
    g_M1[e*128+d]=a*0.08838834764831845f;
}

// LN of row `w` (guarded by caller) from sq into sz
static __device__ __forceinline__ void ln_row(const float (*sq)[128], float (*sz)[128],
        const float* gq, const float* bq, int w, int l){
    float4 y4=((const float4*)sq[w])[l];
    float s=y4.x+y4.y+y4.z+y4.w;
    float s2=fmaf(y4.x,y4.x,fmaf(y4.y,y4.y,fmaf(y4.z,y4.z,y4.w*y4.w)));
#pragma unroll
    for(int d=16;d>0;d>>=1){s+=__shfl_xor_sync(FULL,s,d);s2+=__shfl_xor_sync(FULL,s2,d);}
    float m=s*(1.f/128.f);
    float rstd=rsqrtf(fmaf(s2,1.f/128.f,-m*m)+1e-5f);
    float4 gg=((const float4*)gq)[l], bb=((const float4*)bq)[l];
    float4 z4;
    z4.x=fmaf((y4.x-m)*rstd,gg.x,bb.x); z4.y=fmaf((y4.y-m)*rstd,gg.y,bb.y);
    z4.z=fmaf((y4.z-m)*rstd,gg.z,bb.z); z4.w=fmaf((y4.w-m)*rstd,gg.w,bb.w);
    ((float4*)sz[w])[l]=z4;
}

// qk projection for NR rows in sz using 256 threads (NR*128 <= 512 assumed per group math)
// c=t&127, each t>>7 group handles NR/2 rows
template<int NR>
static __device__ __forceinline__ void qkproj(const float (*sz)[128], float (*qkraw)[128],
        const float* gkv, const float* bkv, int qbase, int t, int w, int l){
    const int RG=NR/2;
    int c=t&127, rq=(t>>7)*RG;
    float acc[RG];
#pragma unroll
    for(int k=0;k<RG;k++) acc[k]=0.f;
    for(int e=0;e<128;e++){
        float mv=g_M1[e*128+c];
#pragma unroll
        for(int k=0;k<RG;k++) acc[k]=fmaf(sz[rq+k][e],mv,acc[k]);
    }
#pragma unroll
    for(int k=0;k<RG;k++) qkraw[rq+k][c]=acc[k];
    __syncthreads();
    if(w<NR){
        float4 qr=((const float4*)qkraw[w])[l];
        float4 g4=((const float4*)gkv)[l], b4=((const float4*)bkv)[l];
        float c1=dot4(qr,g4), c0=dot4(qr,b4);
#pragma unroll
        for(int d=16;d>0;d>>=1){c1+=__shfl_xor_sync(FULL,c1,d);c0+=__shfl_xor_sync(FULL,c0,d);}
        if(l==0){g_cq1[qbase+w]=c1; g_cq0[qbase+w]=c0;}
        float4 o; o.x=qr.x*g4.x; o.y=qr.y*g4.y; o.z=qr.z*g4.z; o.w=qr.w*g4.w;
        ((float4*)(g_qkg+(qbase+w)*128))[l]=o;
    }
}

__global__ void __launch_bounds__(256) kqk0(const float* __restrict__ gq,
        const float* __restrict__ bq, const float* __restrict__ gkv,
        const float* __restrict__ bkv){
    int qbase=blockIdx.x*8, t=threadIdx.x, w=t>>5, l=t&31;
    __shared__ float sq[8][128], sz[8][128], qkraw[8][128];
#pragma unroll
    for(int k=0;k<4;k++) ((float*)sq)[k*256+t]=g_qstate[qbase*128+k*256+t];
    __syncthreads();
    ln_row(sq,sz,gq,bq,w,l);
    __syncthreads();
    qkproj<8>(sz,qkraw,gkv,bkv,qbase,t,w,l);
}

// ---- stream: grid(8,32), 256 thr, LN-stat caching ----
__global__ void __launch_bounds__(256,2) kstream3(const float* __restrict__ inp,
        float* __restrict__ a0out, int writeA0, int iter0){
    __shared__ float dbuf[512*17];
    __shared__ float rstd_s[512], m_s[512];
    __shared__ float4 qks[16][32];
    __shared__ float t1s[16], t2s[16];
    float* Sblk = (float*)qks;
    int p=blockIdx.x, b=blockIdx.y, t=threadIdx.x, w=t>>5, l=t&31;
    if(t<16){t1s[t]=0.f;t2s[t]=0.f;}
#pragma unroll
    for(int k=0;k<8;k++) ((float*)qks)[k*256+t]=g_qkg[b*2048+k*256+t];
    if(!iter0){
#pragma unroll
        for(int k=0;k<2;k++){
            rstd_s[k*256+t]=g_rstdc[b*4096+p*512+k*256+t];
            m_s[k*256+t]=g_mc[b*4096+p*512+k*256+t];
        }
    }
    __syncthreads();
    {
        float cq1v=g_cq1[b*16+(l>>1)], cq0v=g_cq0[b*16+(l>>1)];
        int rb=w*64;
        const float4* base=(const float4*)(inp+((size_t)b*4096+p*512+rb)*128);
        for(int i=0;i<64;i++){
            float4 x=base[i*32+l];
            float v[16];
#pragma unroll
            for(int q=0;q<16;q++) v[q]=dot4(x,qks[q][l]);
            int row=rb+i;
            float rs,m;
            if(iter0){
                float s=x.x+x.y+x.z+x.w;
                float s2=fmaf(x.x,x.x,fmaf(x.y,x.y,fmaf(x.z,x.z,x.w*x.w)));
#pragma unroll
                for(int d=16;d>0;d>>=1){s+=__shfl_xor_sync(FULL,s,d);s2+=__shfl_xor_sync(FULL,s2,d);}
                m=s*(1.f/128.f);
                rs=rsqrtf(fmaf(s2,1.f/128.f,-m*m)+1e-5f);
                if(l==0){rstd_s[row]=rs;m_s[row]=m;}
            }else{
                rs=rstd_s[row]; m=m_s[row];
            }
            float u1=butterfly16(v,l);
            if((l&1)==0) dbuf[row*17+(l>>1)]=fmaf(rs,fmaf(-m,cq1v,u1),cq0v);
        }
    }
    __syncthreads();
    if(iter0){
#pragma unroll
        for(int k=0;k<2;k++){
            g_rstdc[b*4096+p*512+k*256+t]=rstd_s[k*256+t];
            g_mc[b*4096+p*512+k*256+t]=m_s[k*256+t];
        }
    }
    for(int j=0;j<2;j++){
        int r=t+j*256;
        float rs=rstd_s[r], mv=m_s[r];
        float a0[16], mx=-1e30f;
#pragma unroll
        for(int q=0;q<16;q++){a0[q]=dbuf[r*17+q]; mx=fmaxf(mx,a0[q]);}
        float ssum=0.f;
#pragma unroll
        for(int q=0;q<16;q++){a0[q]=fexp(a0[q]-mx); ssum+=a0[q];}
        float inv=1.f/ssum;
        float t1v[16];
#pragma unroll
        for(int q=0;q<16;q++){
            a0[q]*=inv;
            dbuf[r*17+q]=a0[q]*rs;
            t1v[q]=a0[q]*rs*mv;
        }
        float t2r=butterfly16(a0,l), t1r=butterfly16(t1v,l);
        if((l&1)==0){atomicAdd(&t2s[l>>1],t2r);atomicAdd(&t1s[l>>1],t1r);}
        if(writeA0){
            float* dst=a0out+(size_t)b*65536+p*512+j*256+t;
#pragma unroll
            for(int q=0;q<16;q++) dst[(size_t)q*4096]=a0[q];
        }
    }
    __syncthreads();
    for(int i=t;i<2048;i+=256) Sblk[i]=0.f;
    __syncthreads();
    {
        float4 Sa[16];
#pragma unroll
        for(int q=0;q<16;q++){Sa[q].x=0.f;Sa[q].y=0.f;Sa[q].z=0.f;Sa[q].w=0.f;}
        int rb=w*64;
        const float4* base=(const float4*)(inp+((size_t)b*4096+p*512+rb)*128);
        const float* wb=dbuf+rb*17;
        for(int i=0;i<64;i++){
            float4 x=base[i*32+l];
            const float* wr=wb+i*17;
#pragma unroll
            for(int q=0;q<16;q++){
                float wq=wr[q];
                Sa[q].x=fmaf(wq,x.x,Sa[q].x); Sa[q].y=fmaf(wq,x.y,Sa[q].y);
                Sa[q].z=fmaf(wq,x.z,Sa[q].z); Sa[q].w=fmaf(wq,x.w,Sa[q].w);
            }
        }
#pragma unroll
        for(int q=0;q<16;q++){
            atomicAdd(&Sblk[q*128+4*l+0],Sa[q].x);
            atomicAdd(&Sblk[q*128+4*l+1],Sa[q].y);
            atomicAdd(&Sblk[q*128+4*l+2],Sa[q].z);
            atomicAdd(&Sblk[q*128+4*l+3],Sa[q].w);
        }
    }
    __syncthreads();
    float* tp=g_Tpart+((size_t)(b*8+p))*2048;
    for(int i=t;i<2048;i+=256) tp[i]=Sblk[i];
    if(t<16){g_t1p[(b*8+p)*16+t]=t1s[t];g_t2p[(b*8+p)*16+t]=t2s[t];}
}

// ---- fused tail: 128 blocks x 256 thr, 4 rows/block, float4 math ----
__global__ void __launch_bounds__(256) ktail(const float* __restrict__ Wv,
        const float* __restrict__ gkv, const float* __restrict__ bkv,
        const float* __restrict__ wih, const float* __restrict__ whh,
        const float* __restrict__ bih, const float* __restrict__ bhh,
        const float* __restrict__ g2, const float* __restrict__ b2ln,
        const float* __restrict__ w1, const float* __restrict__ b1,
        const float* __restrict__ w2, const float* __restrict__ b2f,
        const float* __restrict__ gq, const float* __restrict__ bq,
        float* __restrict__ qout, int last){
    int blk=blockIdx.x, b=blk>>2, qh=(blk&3)*4;
    int t=threadIdx.x, w=t>>5, l=t&31;
    __shared__ float Sh[4][128], su[4][128], sx[4][128], sy[4][128], sh1[4][512];
    __shared__ float t1a[4], t2a[4], rsa[4];
    if(t<4){
        float s1=0.f,s2=0.f;
        for(int p=0;p<8;p++){
            s1+=g_t1p[(b*8+p)*16+qh+t];
            s2+=g_t2p[(b*8+p)*16+qh+t];
        }
        t1a[t]=s1; t2a[t]=s2; rsa[t]=1.f/(s2+1e-5f);
    }
#pragma unroll
    for(int k=0;k<2;k++)
        ((float*)sx)[k*256+t]=g_qstate[(b*16+qh)*128+k*256+t];
    __syncthreads();
    // S reduce + kv-LN correction
#pragma unroll
    for(int k=0;k<2;k++){
        int idx=k*256+t, q=idx>>7, c=idx&127;
        float a=0.f;
        for(int p=0;p<8;p++) a+=g_Tpart[((size_t)(b*8+p))*2048+(qh+q)*128+c];
        ((float*)Sh)[idx]=fmaf(gkv[c],a-t1a[q],bkv[c]*t2a[q]);
    }
    __syncthreads();
    // u = Sh @ Wv^T * rs   (2 rows per thread)
    {
        int c=t&127, qg=(t>>7)*2;
        float acc0=0.f, acc1=0.f;
        const float4* wr=(const float4*)(Wv+(size_t)c*128);
        for(int d=0;d<32;d++){
            float4 wv=wr[d];
            acc0+=dot4(((const float4*)Sh[qg])[d],wv);
            acc1+=dot4(((const float4*)Sh[qg+1])[d],wv);
        }
        su[qg][c]=acc0*rsa[qg];
        su[qg+1][c]=acc1*rsa[qg+1];
    }
    __syncthreads();
    // GRU -> sy   (2 rows per thread)
    {
        int c=t&127, rh=(t>>7)*2;
        float aIR[2]={0,0},aIZ[2]={0,0},aIN[2]={0,0};
        float aHR[2]={0,0},aHZ[2]={0,0},aHN[2]={0,0};
        const float4* wir=(const float4*)(wih+(size_t)c*128);
        const float4* wiz=(const float4*)(wih+(size_t)(c+128)*128);
        const float4* win=(const float4*)(wih+(size_t)(c+256)*128);
        const float4* whr=(const float4*)(whh+(size_t)c*128);
        const float4* whz=(const float4*)(whh+(size_t)(c+128)*128);
        const float4* whn=(const float4*)(whh+(size_t)(c+256)*128);
        for(int d=0;d<32;d++){
            float4 w0=wir[d],w1_=wiz[d],w2_=win[d],w3=whr[d],w4=whz[d],w5=whn[d];
#pragma unroll
            for(int k=0;k<2;k++){
                float4 u4=((const float4*)su[rh+k])[d], x4=((const float4*)sx[rh+k])[d];
                aIR[k]+=dot4(u4,w0); aIZ[k]+=dot4(u4,w1_); aIN[k]+=dot4(u4,w2_);
                aHR[k]+=dot4(x4,w3); aHZ[k]+=dot4(x4,w4); aHN[k]+=dot4(x4,w5);
            }
        }
        float bir=bih[c],biz=bih[c+128],bin=bih[c+256];
        float bhr=bhh[c],bhz=bhh[c+128],bhn=bhh[c+256];
#pragma unroll
        for(int k=0;k<2;k++){
            float rr=1.f/(1.f+fexp(-(aIR[k]+bir+aHR[k]+bhr)));
            float zz=1.f/(1.f+fexp(-(aIZ[k]+biz+aHZ[k]+bhz)));
            float nn=tanhf(aIN[k]+bin+rr*(aHN[k]+bhn));
            sy[rh+k][c]=(1.f-zz)*nn+zz*sx[rh+k][c];
        }
    }
    __syncthreads();
    if(w<4) ln_row(sy,Sh,g2,b2ln,w,l);
    __syncthreads();
    // FFN1 -> sh1 : outputs t and t+256 for 4 rows
    {
        float acc0[4]={0,0,0,0}, acc1[4]={0,0,0,0};
        const float4* wa=(const float4*)(w1+(size_t)t*128);
        const float4* wb=(const float4*)(w1+(size_t)(t+256)*128);
        for(int d=0;d<32;d++){
            float4 a=wa[d], bb=wb[d];
#pragma unroll
            for(int r=0;r<4;r++){
                float4 zz=((const float4*)Sh[r])[d];
                acc0[r]+=dot4(zz,a); acc1[r]+=dot4(zz,bb);
            }
        }
        float b0=b1[t], b256=b1[t+256];
#pragma unroll
        for(int r=0;r<4;r++){
            sh1[r][t]=fmaxf(acc0[r]+b0,0.f);
            sh1[r][t+256]=fmaxf(acc1[r]+b256,0.f);
        }
    }
    __syncthreads();
    // FFN2 + residual (2 rows per thread)
    {
        int c=t&127, rh=(t>>7)*2;
        float acc0=0.f, acc1=0.f;
        const float4* wp=(const float4*)(w2+(size_t)c*512);
        for(int d=0;d<128;d++){
            float4 wv=wp[d];
            acc0+=dot4(((const float4*)sh1[rh])[d],wv);
            acc1+=dot4(((const float4*)sh1[rh+1])[d],wv);
        }
        float bb=b2f[c];
        float v0=sy[rh][c]+acc0+bb;
        float v1=sy[rh+1][c]+acc1+bb;
        g_qstate[(b*16+qh+rh)*128+c]=v0;
        g_qstate[(b*16+qh+rh+1)*128+c]=v1;
        su[rh][c]=v0; su[rh+1][c]=v1;
        if(last){
            qout[(b*16+qh+rh)*128+c]=v0;
            qout[(b*16+qh+rh+1)*128+c]=v1;
        }
    }
    __syncthreads();
    if(last) return;
    if(w<4) ln_row(su,sy,gq,bq,w,l);
    __syncthreads();
    qkproj<4>(sy,Sh,gkv,bkv,b*16+qh,t,w,l);
}

extern "C" void kernel_launch(void* const* d_in, const int* in_sizes, int n_in,
                              void* d_out, int out_size){
    const float* inp=(const float*)d_in[0];
    const float* query=(const float*)d_in[1];
    const float* ln_kv_g=(const float*)d_in[2];
    const float* ln_kv_b=(const float*)d_in[3];
    const float* Wk=(const float*)d_in[4];
    const float* Wv=(const float*)d_in[5];
    const float* ln_q_g=(const float*)d_in[6];
    const float* ln_q_b=(const float*)d_in[7];
    const float* Wq=(const float*)d_in[8];
    const float* gru_wih=(const float*)d_in[9];
    const float* gru_whh=(const float*)d_in[10];
    const float* gru_bih=(const float*)d_in[11];
    const float* gru_bhh=(const float*)d_in[12];
    const float* ln2_g=(const float*)d_in[13];
    const float* ln2_b=(const float*)d_in[14];
    const float* ffn_w1=(const float*)d_in[15];
    const float* ffn_b1=(const float*)d_in[16];
    const float* ffn_w2=(const float*)d_in[17];
    const float* ffn_b2=(const float*)d_in[18];
    float* out=(float*)d_out;
    float* a0out=out+32*16*128;

    kM1<<<128,128>>>(Wq,Wk);
    kcopy<<<512,128>>>(query);
    kqk0<<<64,256>>>(ln_q_g,ln_q_b,ln_kv_g,ln_kv_b);
    for(int it=0;it<3;it++){
        int last=(it==2);
        kstream3<<<dim3(8,32),256>>>(inp,a0out,last,it==0);
        ktail<<<128,256>>>(Wv,ln_kv_g,ln_kv_b,gru_wih,gru_whh,gru_bih,gru_bhh,
                           ln2_g,ln2_b,ffn_w1,ffn_b1,ffn_w2,ffn_b2,
                           ln_q_g,ln_q_b,out,last);
    }
}

// round 8
// speedup vs baseline: 1.7085x; 1.1667x over previous
#include <cuda_runtime.h>
#include <math.h>
#define FULL 0xffffffffu

__device__ float g_M1[128*128];
__device__ float g_qstate[32*16*128];
__device__ float g_qkg[32*16*128];
__device__ float g_cq1[32*16];
__device__ float g_cq0[32*16];
__device__ float g_Tpart[32*8*16*128];
__device__ float g_t1p[32*8*16];
__device__ float g_t2p[32*8*16];
__device__ float g_rstdc[32*4096];
__device__ float g_mc[32*4096];

static __device__ __forceinline__ float dot4(float4 a, float4 b) {
    return fmaf(a.x,b.x,fmaf(a.y,b.y,fmaf(a.z,b.z,a.w*b.w)));
}
static __device__ __forceinline__ unsigned tf32r(float x){
    unsigned u; asm("cvt.rna.tf32.f32 %0, %1;" : "=r"(u) : "f"(x)); return u;
}
#define MMA1688(D,A0,A1,A2,A3,B0,B1) \
  asm volatile("mma.sync.aligned.m16n8k8.row.col.f32.tf32.tf32.f32 " \
    "{%0,%1,%2,%3},{%4,%5,%6,%7},{%8,%9},{%0,%1,%2,%3};" \
    : "+f"(D[0]),"+f"(D[1]),"+f"(D[2]),"+f"(D[3]) \
    : "r"(A0),"r"(A1),"r"(A2),"r"(A3),"r"(B0),"r"(B1))

static __device__ __forceinline__ float butterfly16(const float* v, int l) {
    float u8[8];
    { bool hi=(l&16);
#pragma unroll
      for(int j=0;j<8;j++){float mi=hi?v[j+8]:v[j],ot=hi?v[j]:v[j+8];
        u8[j]=mi+__shfl_xor_sync(FULL,ot,16);} }
    float u4[4];
    { bool hi=(l&8);
#pragma unroll
      for(int j=0;j<4;j++){float mi=hi?u8[j+4]:u8[j],ot=hi?u8[j]:u8[j+4];
        u4[j]=mi+__shfl_xor_sync(FULL,ot,8);} }
    float u2[2];
    { bool hi=(l&4);
#pragma unroll
      for(int j=0;j<2;j++){float mi=hi?u4[j+2]:u4[j],ot=hi?u4[j]:u4[j+2];
        u2[j]=mi+__shfl_xor_sync(FULL,ot,4);} }
    float u1;
    { bool hi=(l&2);
      float mi=hi?u2[1]:u2[0],ot=hi?u2[0]:u2[1];
      u1=mi+__shfl_xor_sync(FULL,ot,2); }
    return u1+__shfl_xor_sync(FULL,u1,1);
}
static __device__ __forceinline__ float fexp(float x) {
    x = fmaxf(x, -87.f);
    float t = fmaf(x, 1.4426950408889634f, 12582912.f);
    int ni = __float_as_int(t) - 0x4B400000;
    float n = t - 12582912.f;
    float f = fmaf(x, 1.4426950408889634f, -n);
    float p = 1.5403530e-4f;
    p = fmaf(p,f,1.3333558e-3f); p = fmaf(p,f,9.6181291e-3f);
    p = fmaf(p,f,5.5504109e-2f); p = fmaf(p,f,2.4022651e-1f);
    p = fmaf(p,f,6.9314718e-1f); p = fmaf(p,f,1.f);
    return p * __int_as_float((ni + 127) << 23);
}

__global__ void kcopy(const float* __restrict__ s){
    int i = blockIdx.x*128+threadIdx.x; g_qstate[i]=s[i];
}
__global__ void kM1(const float* __restrict__ Wq, const float* __restrict__ Wk){
    int e=blockIdx.x, d=threadIdx.x; float a=0.f;
    for(int c=0;c<128;c++) a=fmaf(Wq[c*128+e],Wk[c*128+d],a);
    g_M1[e*128+d]=a*0.08838834764831845f;
}

static __device__ __forceinline__ void ln_row(const float (*sq)[128], float (*sz)[128],
        const float* gq, const float* bq, int w, int l){
    float4 y4=((const float4*)sq[w])[l];
    float s=y4.x+y4.y+y4.z+y4.w;
    float s2=fmaf(y4.x,y4.x,fmaf(y4.y,y4.y,fmaf(y4.z,y4.z,y4.w*y4.w)));
#pragma unroll
    for(int d=16;d>0;d>>=1){s+=__shfl_xor_sync(FULL,s,d);s2+=__shfl_xor_sync(FULL,s2,d);}
    float m=s*(1.f/128.f);
    float rstd=rsqrtf(fmaf(s2,1.f/128.f,-m*m)+1e-5f);
    float4 gg=((const float4*)gq)[l], bb=((const float4*)bq)[l];
    float4 z4;
    z4.x=fmaf((y4.x-m)*rstd,gg.x,bb.x); z4.y=fmaf((y4.y-m)*rstd,gg.y,bb.y);
    z4.z=fmaf((y4.z-m)*rstd,gg.z,bb.z); z4.w=fmaf((y4.w-m)*rstd,gg.w,bb.w);
    ((float4*)sz[w])[l]=z4;
}

template<int NR>
static __device__ __forceinline__ void qkproj(const float (*sz)[128], float (*qkraw)[128],
        const float* gkv, const float* bkv, int qbase, int t, int w, int l){
    const int RG=NR/2;
    int c=t&127, rq=(t>>7)*RG;
    float acc[RG];
#pragma unroll
    for(int k=0;k<RG;k++) acc[k]=0.f;
    for(int e=0;e<128;e++){
        float mv=g_M1[e*128+c];
#pragma unroll
        for(int k=0;k<RG;k++) acc[k]=fmaf(sz[rq+k][e],mv,acc[k]);
    }
#pragma unroll
    for(int k=0;k<RG;k++) qkraw[rq+k][c]=acc[k];
    __syncthreads();
    if(w<NR){
        float4 qr=((const float4*)qkraw[w])[l];
        float4 g4=((const float4*)gkv)[l], b4=((const float4*)bkv)[l];
        float c1=dot4(qr,g4), c0=dot4(qr,b4);
#pragma unroll
        for(int d=16;d>0;d>>=1){c1+=__shfl_xor_sync(FULL,c1,d);c0+=__shfl_xor_sync(FULL,c0,d);}
        if(l==0){g_cq1[qbase+w]=c1; g_cq0[qbase+w]=c0;}
        float4 o; o.x=qr.x*g4.x; o.y=qr.y*g4.y; o.z=qr.z*g4.z; o.w=qr.w*g4.w;
        ((float4*)(g_qkg+(qbase+w)*128))[l]=o;
    }
}

__global__ void __launch_bounds__(256) kqk0(const float* __restrict__ gq,
        const float* __restrict__ bq, const float* __restrict__ gkv,
        const float* __restrict__ bkv){
    int qbase=blockIdx.x*8, t=threadIdx.x, w=t>>5, l=t&31;
    __shared__ float sq[8][128], sz[8][128], qkraw[8][128];
#pragma unroll
    for(int k=0;k<4;k++) ((float*)sq)[k*256+t]=g_qstate[qbase*128+k*256+t];
    __syncthreads();
    ln_row(sq,sz,gq,bq,w,l);
    __syncthreads();
    qkproj<8>(sz,qkraw,gkv,bkv,qbase,t,w,l);
}

// smem float offsets
#define QKF  0
#define DBUF 2048
#define RSTD 10240
#define MS   10752
#define STG  11264
#define T1   19456
#define T2   19472
#define CQ1  19488
#define CQ0  19504
#define SMEMF 19520

// ---- stream: grid(8,32), 256 thr, phase1 on tensor cores ----
__global__ void __launch_bounds__(256,2) kstream5(const float* __restrict__ inp,
        float* __restrict__ a0out, int writeA0, int iter0){
    extern __shared__ float sm[];
    int p=blockIdx.x, b=blockIdx.y, t=threadIdx.x, w=t>>5, l=t&31;
    if(t<16){
        sm[T1+t]=0.f; sm[T2+t]=0.f;
        sm[CQ1+t]=g_cq1[b*16+t]; sm[CQ0+t]=g_cq0[b*16+t];
    }
    // B fragments (tf32) from qkg
#pragma unroll
    for(int e=0;e<8;e++){
        int gi=e*256+t;
        int j=gi&1, lane=(gi>>1)&31, kn=gi>>6;
        int k=kn>>1, nt=kn&1;
        int slot=nt*8+(lane>>2), ch=k*8+(lane&3)+j*4;
        sm[QKF+gi]=__uint_as_float(tf32r(g_qkg[b*2048+slot*128+ch]));
    }
    if(!iter0){
#pragma unroll
        for(int k=0;k<2;k++){
            sm[RSTD+k*256+t]=g_rstdc[b*4096+p*512+k*256+t];
            sm[MS+k*256+t]=g_mc[b*4096+p*512+k*256+t];
        }
    }
    __syncthreads();
    int rb=w*64;
    const float4* base=(const float4*)(inp+((size_t)b*4096+p*512+rb)*128);
    if(iter0){
        for(int i=0;i<64;i++){
            float4 x=base[i*32+l];
            float s=x.x+x.y+x.z+x.w;
            float s2=fmaf(x.x,x.x,fmaf(x.y,x.y,fmaf(x.z,x.z,x.w*x.w)));
#pragma unroll
            for(int d=16;d>0;d>>=1){s+=__shfl_xor_sync(FULL,s,d);s2+=__shfl_xor_sync(FULL,s2,d);}
            float m=s*(1.f/128.f);
            float rs=rsqrtf(fmaf(s2,1.f/128.f,-m*m)+1e-5f);
            if(l==0){sm[RSTD+rb+i]=rs;sm[MS+rb+i]=m;}
        }
        __syncwarp();
    }
    // ---- phase 1: tf32 MMA ----
    {
        int g=l>>2, c4=l&3;
        int wst=STG+w*1024;
        int s0=c4<<1;
        float cqa1[4],cqa0[4];
        cqa1[0]=sm[CQ1+s0];   cqa1[1]=sm[CQ1+s0+1];
        cqa1[2]=sm[CQ1+s0+8]; cqa1[3]=sm[CQ1+s0+9];
        cqa0[0]=sm[CQ0+s0];   cqa0[1]=sm[CQ0+s0+1];
        cqa0[2]=sm[CQ0+s0+8]; cqa0[3]=sm[CQ0+s0+9];
        for(int tile=0;tile<4;tile++){
            int rb16=rb+tile*16;
            const float4* gsrc=(const float4*)(inp+((size_t)b*4096+p*512+rb16)*128);
            float d0[4]={0,0,0,0}, d1[4]={0,0,0,0};
            for(int half=0;half<2;half++){
                // stage 16 rows x 64 ch (tf32-rounded, swizzled)
#pragma unroll
                for(int ii=0;ii<8;ii++){
                    int row=ii*2+(l>>4);
                    float4 x=gsrc[row*32+half*16+(l&15)];
                    uint4 xv;
                    xv.x=tf32r(x.x); xv.y=tf32r(x.y); xv.z=tf32r(x.z); xv.w=tf32r(x.w);
                    int off=wst+row*64+(((l&15)*4)^((row&7)<<2));
                    *(uint4*)(sm+off)=xv;
                }
                __syncwarp();
                int abase=wst+g*64;
#pragma unroll
                for(int kk=0;kk<8;kk++){
                    int k=half*8+kk;
                    int x0=((kk*8)+c4)^(g<<2);
                    unsigned a0=__float_as_uint(sm[abase+x0]);
                    unsigned a1=__float_as_uint(sm[abase+512+x0]);
                    unsigned a2=__float_as_uint(sm[abase+(x0^4)]);
                    unsigned a3=__float_as_uint(sm[abase+512+(x0^4)]);
                    float2 bb=*(const float2*)&sm[QKF+(k*2+0)*64+l*2];
                    MMA1688(d0,a0,a1,a2,a3,__float_as_uint(bb.x),__float_as_uint(bb.y));
                    float2 bc=*(const float2*)&sm[QKF+(k*2+1)*64+l*2];
                    MMA1688(d1,a0,a1,a2,a3,__float_as_uint(bc.x),__float_as_uint(bc.y));
                }
                __syncwarp();
            }
            int r0=rb16+g, r1=r0+8;
            float rs0=sm[RSTD+r0], m0=sm[MS+r0];
            float rs1=sm[RSTD+r1], m1=sm[MS+r1];
            float2 o;
            o.x=fmaf(rs0,fmaf(-m0,cqa1[0],d0[0]),cqa0[0]);
            o.y=fmaf(rs0,fmaf(-m0,cqa1[1],d0[1]),cqa0[1]);
            *(float2*)&sm[DBUF+r0*16+s0]=o;
            o.x=fmaf(rs1,fmaf(-m1,cqa1[0],d0[2]),cqa0[0]);
            o.y=fmaf(rs1,fmaf(-m1,cqa1[1],d0[3]),cqa0[1]);
            *(float2*)&sm[DBUF+r1*16+s0]=o;
            o.x=fmaf(rs0,fmaf(-m0,cqa1[2],d1[0]),cqa0[2]);
            o.y=fmaf(rs0,fmaf(-m0,cqa1[3],d1[1]),cqa0[3]);
            *(float2*)&sm[DBUF+r0*16+8+s0]=o;
            o.x=fmaf(rs1,fmaf(-m1,cqa1[2],d1[2]),cqa0[2]);
            o.y=fmaf(rs1,fmaf(-m1,cqa1[3],d1[3]),cqa0[3]);
            *(float2*)&sm[DBUF+r1*16+8+s0]=o;
        }
    }
    __syncthreads();
    if(iter0){
#pragma unroll
        for(int k=0;k<2;k++){
            g_rstdc[b*4096+p*512+k*256+t]=sm[RSTD+k*256+t];
            g_mc[b*4096+p*512+k*256+t]=sm[MS+k*256+t];
        }
    }
    // ---- phase 2: softmax per row ----
    for(int j=0;j<2;j++){
        int r=t+j*256;
        float rs=sm[RSTD+r], mv=sm[MS+r];
        float a0[16], mx=-1e30f;
#pragma unroll
        for(int q=0;q<16;q++){a0[q]=sm[DBUF+r*16+q]; mx=fmaxf(mx,a0[q]);}
        float ssum=0.f;
#pragma unroll
        for(int q=0;q<16;q++){a0[q]=fexp(a0[q]-mx); ssum+=a0[q];}
        float inv=1.f/ssum;
        float t1v[16];
#pragma unroll
        for(int q=0;q<16;q++){
            a0[q]*=inv;
            sm[DBUF+r*16+q]=a0[q]*rs;
            t1v[q]=a0[q]*rs*mv;
        }
        float t2r=butterfly16(a0,l), t1r=butterfly16(t1v,l);
        if((l&1)==0){atomicAdd(&sm[T2+(l>>1)],t2r);atomicAdd(&sm[T1+(l>>1)],t1r);}
        if(writeA0){
            float* dst=a0out+(size_t)b*65536+p*512+j*256+t;
#pragma unroll
            for(int q=0;q<16;q++) dst[(size_t)q*4096]=a0[q];
        }
    }
    __syncthreads();
    // ---- phase 3: S += w*x (fp32) ----
    float* Sblk=sm+QKF;
    for(int i=t;i<2048;i+=256) Sblk[i]=0.f;
    __syncthreads();
    {
        float4 Sa[16];
#pragma unroll
        for(int q=0;q<16;q++){Sa[q].x=0.f;Sa[q].y=0.f;Sa[q].z=0.f;Sa[q].w=0.f;}
        const float* wb=sm+DBUF+rb*16;
        for(int i=0;i<64;i++){
            float4 x=base[i*32+l];
            const float* wr=wb+i*16;
#pragma unroll
            for(int q=0;q<16;q++){
                float wq=wr[q];
                Sa[q].x=fmaf(wq,x.x,Sa[q].x); Sa[q].y=fmaf(wq,x.y,Sa[q].y);
                Sa[q].z=fmaf(wq,x.z,Sa[q].z); Sa[q].w=fmaf(wq,x.w,Sa[q].w);
            }
        }
#pragma unroll
        for(int q=0;q<16;q++){
            atomicAdd(&Sblk[q*128+4*l+0],Sa[q].x);
            atomicAdd(&Sblk[q*128+4*l+1],Sa[q].y);
            atomicAdd(&Sblk[q*128+4*l+2],Sa[q].z);
            atomicAdd(&Sblk[q*128+4*l+3],Sa[q].w);
        }
    }
    __syncthreads();
    float* tp=g_Tpart+((size_t)(b*8+p))*2048;
    for(int i=t;i<2048;i+=256) tp[i]=Sblk[i];
    if(t<16){g_t1p[(b*8+p)*16+t]=sm[T1+t];g_t2p[(b*8+p)*16+t]=sm[T2+t];}
}

// ---- fused tail: unchanged R7 (128 blocks x 256 thr, 4 rows/block) ----
__global__ void __launch_bounds__(256) ktail(const float* __restrict__ Wv,
        const float* __restrict__ gkv, const float* __restrict__ bkv,
        const float* __restrict__ wih, const float* __restrict__ whh,
        const float* __restrict__ bih, const float* __restrict__ bhh,
        const float* __restrict__ g2, const float* __restrict__ b2ln,
        const float* __restrict__ w1, const float* __restrict__ b1,
        const float* __restrict__ w2, const float* __restrict__ b2f,
        const float* __restrict__ gq, const float* __restrict__ bq,
        float* __restrict__ qout, int last){
    int blk=blockIdx.x, b=blk>>2, qh=(blk&3)*4;
    int t=threadIdx.x, w=t>>5, l=t&31;
    __shared__ float Sh[4][128], su[4][128], sx[4][128], sy[4][128], sh1[4][512];
    __shared__ float t1a[4], t2a[4], rsa[4];
    if(t<4){
        float s1=0.f,s2=0.f;
        for(int p=0;p<8;p++){
            s1+=g_t1p[(b*8+p)*16+qh+t];
            s2+=g_t2p[(b*8+p)*16+qh+t];
        }
        t1a[t]=s1; t2a[t]=s2; rsa[t]=1.f/(s2+1e-5f);
    }
#pragma unroll
    for(int k=0;k<2;k++)
        ((float*)sx)[k*256+t]=g_qstate[(b*16+qh)*128+k*256+t];
    __syncthreads();
#pragma unroll
    for(int k=0;k<2;k++){
        int idx=k*256+t, q=idx>>7, c=idx&127;
        float a=0.f;
        for(int p=0;p<8;p++) a+=g_Tpart[((size_t)(b*8+p))*2048+(qh+q)*128+c];
        ((float*)Sh)[idx]=fmaf(gkv[c],a-t1a[q],bkv[c]*t2a[q]);
    }
    __syncthreads();
    {
        int c=t&127, qg=(t>>7)*2;
        float acc0=0.f, acc1=0.f;
        const float4* wr=(const float4*)(Wv+(size_t)c*128);
        for(int d=0;d<32;d++){
            float4 wv=wr[d];
            acc0+=dot4(((const float4*)Sh[qg])[d],wv);
            acc1+=dot4(((const float4*)Sh[qg+1])[d],wv);
        }
        su[qg][c]=acc0*rsa[qg];
        su[qg+1][c]=acc1*rsa[qg+1];
    }
    __syncthreads();
    {
        int c=t&127, rh=(t>>7)*2;
        float aIR[2]={0,0},aIZ[2]={0,0},aIN[2]={0,0};
        float aHR[2]={0,0},aHZ[2]={0,0},aHN[2]={0,0};
        const float4* wir=(const float4*)(wih+(size_t)c*128);
        const float4* wiz=(const float4*)(wih+(size_t)(c+128)*128);
        const float4* win=(const float4*)(wih+(size_t)(c+256)*128);
        const float4* whr=(const float4*)(whh+(size_t)c*128);
        const float4* whz=(const float4*)(whh+(size_t)(c+128)*128);
        const float4* whn=(const float4*)(whh+(size_t)(c+256)*128);
        for(int d=0;d<32;d++){
            float4 w0=wir[d],w1_=wiz[d],w2_=win[d],w3=whr[d],w4=whz[d],w5=whn[d];
#pragma unroll
            for(int k=0;k<2;k++){
                float4 u4=((const float4*)su[rh+k])[d], x4=((const float4*)sx[rh+k])[d];
                aIR[k]+=dot4(u4,w0); aIZ[k]+=dot4(u4,w1_); aIN[k]+=dot4(u4,w2_);
                aHR[k]+=dot4(x4,w3); aHZ[k]+=dot4(x4,w4); aHN[k]+=dot4(x4,w5);
            }
        }
        float bir=bih[c],biz=bih[c+128],bin=bih[c+256];
        float bhr=bhh[c],bhz=bhh[c+128],bhn=bhh[c+256];
#pragma unroll
        for(int k=0;k<2;k++){
            float rr=1.f/(1.f+fexp(-(aIR[k]+bir+aHR[k]+bhr)));
            float zz=1.f/(1.f+fexp(-(aIZ[k]+biz+aHZ[k]+bhz)));
            float nn=tanhf(aIN[k]+bin+rr*(aHN[k]+bhn));
            sy[rh+k][c]=(1.f-zz)*nn+zz*sx[rh+k][c];
        }
    }
    __syncthreads();
    if(w<4) ln_row(sy,Sh,g2,b2ln,w,l);
    __syncthreads();
    {
        float acc0[4]={0,0,0,0}, acc1[4]={0,0,0,0};
        const float4* wa=(const float4*)(w1+(size_t)t*128);
        const float4* wb=(const float4*)(w1+(size_t)(t+256)*128);
        for(int d=0;d<32;d++){
            float4 a=wa[d], bb=wb[d];
#pragma unroll
            for(int r=0;r<4;r++){
                float4 zz=((const float4*)Sh[r])[d];
                acc0[r]+=dot4(zz,a); acc1[r]+=dot4(zz,bb);
            }
        }
        float b0=b1[t], b256=b1[t+256];
#pragma unroll
        for(int r=0;r<4;r++){
            sh1[r][t]=fmaxf(acc0[r]+b0,0.f);
            sh1[r][t+256]=fmaxf(acc1[r]+b256,0.f);
        }
    }
    __syncthreads();
    {
        int c=t&127, rh=(t>>7)*2;
        float acc0=0.f, acc1=0.f;
        const float4* wp=(const float4*)(w2+(size_t)c*512);
        for(int d=0;d<128;d++){
            float4 wv=wp[d];
            acc0+=dot4(((const float4*)sh1[rh])[d],wv);
            acc1+=dot4(((const float4*)sh1[rh+1])[d],wv);
        }
        float bb=b2f[c];
        float v0=sy[rh][c]+acc0+bb;
        float v1=sy[rh+1][c]+acc1+bb;
        g_qstate[(b*16+qh+rh)*128+c]=v0;
        g_qstate[(b*16+qh+rh+1)*128+c]=v1;
        su[rh][c]=v0; su[rh+1][c]=v1;
        if(last){
            qout[(b*16+qh+rh)*128+c]=v0;
            qout[(b*16+qh+rh+1)*128+c]=v1;
        }
    }
    __syncthreads();
    if(last) return;
    if(w<4) ln_row(su,sy,gq,bq,w,l);
    __syncthreads();
    qkproj<4>(sy,Sh,gkv,bkv,b*16+qh,t,w,l);
}

extern "C" void kernel_launch(void* const* d_in, const int* in_sizes, int n_in,
                              void* d_out, int out_size){
    const float* inp=(const float*)d_in[0];
    const float* query=(const float*)d_in[1];
    const float* ln_kv_g=(const float*)d_in[2];
    const float* ln_kv_b=(const float*)d_in[3];
    const float* Wk=(const float*)d_in[4];
    const float* Wv=(const float*)d_in[5];
    const float* ln_q_g=(const float*)d_in[6];
    const float* ln_q_b=(const float*)d_in[7];
    const float* Wq=(const float*)d_in[8];
    const float* gru_wih=(const float*)d_in[9];
    const float* gru_whh=(const float*)d_in[10];
    const float* gru_bih=(const float*)d_in[11];
    const float* gru_bhh=(const float*)d_in[12];
    const float* ln2_g=(const float*)d_in[13];
    const float* ln2_b=(const float*)d_in[14];
    const float* ffn_w1=(const float*)d_in[15];
    const float* ffn_b1=(const float*)d_in[16];
    const float* ffn_w2=(const float*)d_in[17];
    const float* ffn_b2=(const float*)d_in[18];
    float* out=(float*)d_out;
    float* a0out=out+32*16*128;

    int smemB = SMEMF*4;
    cudaFuncSetAttribute(kstream5, cudaFuncAttributeMaxDynamicSharedMemorySize, smemB);
    kM1<<<128,128>>>(Wq,Wk);
    kcopy<<<512,128>>>(query);
    kqk0<<<64,256>>>(ln_q_g,ln_q_b,ln_kv_g,ln_kv_b);
    for(int it=0;it<3;it++){
        int last=(it==2);
        kstream5<<<dim3(8,32),256,smemB>>>(inp,a0out,last,it==0);
        ktail<<<128,256>>>(Wv,ln_kv_g,ln_kv_b,gru_wih,gru_whh,gru_bih,gru_bhh,
                           ln2_g,ln2_b,ffn_w1,ffn_b1,ffn_w2,ffn_b2,
                           ln_q_g,ln_q_b,out,last);
    }
}

// round 9
// speedup vs baseline: 1.7500x; 1.0243x over previous
#include <cuda_runtime.h>
#include <math.h>
#define FULL 0xffffffffu

__device__ float g_M1[128*128];
__device__ float g_qstate[32*16*128];
__device__ float g_qkg[32*16*128];
__device__ float g_cq1[32*16];
__device__ float g_cq0[32*16];
__device__ float g_Tpart[32*8*16*128];
__device__ float g_t1p[32*8*16];
__device__ float g_t2p[32*8*16];
__device__ float g_rstdc[32*4096];
__device__ float g_mc[32*4096];

static __device__ __forceinline__ float dot4(float4 a, float4 b) {
    return fmaf(a.x,b.x,fmaf(a.y,b.y,fmaf(a.z,b.z,a.w*b.w)));
}
static __device__ __forceinline__ unsigned tf32r(float x){
    unsigned u; asm("cvt.rna.tf32.f32 %0, %1;" : "=r"(u) : "f"(x)); return u;
}
#define MMA1688(D,A0,A1,A2,A3,B0,B1) \
  asm volatile("mma.sync.aligned.m16n8k8.row.col.f32.tf32.tf32.f32 " \
    "{%0,%1,%2,%3},{%4,%5,%6,%7},{%8,%9},{%0,%1,%2,%3};" \
    : "+f"(D[0]),"+f"(D[1]),"+f"(D[2]),"+f"(D[3]) \
    : "r"(A0),"r"(A1),"r"(A2),"r"(A3),"r"(B0),"r"(B1))

static __device__ __forceinline__ float fexp(float x) {
    x = fmaxf(x, -87.f);
    float t = fmaf(x, 1.4426950408889634f, 12582912.f);
    int ni = __float_as_int(t) - 0x4B400000;
    float n = t - 12582912.f;
    float f = fmaf(x, 1.4426950408889634f, -n);
    float p = 1.5403530e-4f;
    p = fmaf(p,f,1.3333558e-3f); p = fmaf(p,f,9.6181291e-3f);
    p = fmaf(p,f,5.5504109e-2f); p = fmaf(p,f,2.4022651e-1f);
    p = fmaf(p,f,6.9314718e-1f); p = fmaf(p,f,1.f);
    return p * __int_as_float((ni + 127) << 23);
}

__global__ void kcopy(const float* __restrict__ s){
    int i = blockIdx.x*128+threadIdx.x; g_qstate[i]=s[i];
}
__global__ void kM1(const float* __restrict__ Wq, const float* __restrict__ Wk){
    int e=blockIdx.x, d=threadIdx.x; float a=0.f;
    for(int c=0;c<128;c++) a=fmaf(Wq[c*128+e],Wk[c*128+d],a);
    g_M1[e*128+d]=a*0.08838834764831845f;
}

static __device__ __forceinline__ void ln_row(const float (*sq)[128], float (*sz)[128],
        const float* gq, const float* bq, int w, int l){
    float4 y4=((const float4*)sq[w])[l];
    float s=y4.x+y4.y+y4.z+y4.w;
    float s2=fmaf(y4.x,y4.x,fmaf(y4.y,y4.y,fmaf(y4.z,y4.z,y4.w*y4.w)));
#pragma unroll
    for(int d=16;d>0;d>>=1){s+=__shfl_xor_sync(FULL,s,d);s2+=__shfl_xor_sync(FULL,s2,d);}
    float m=s*(1.f/128.f);
    float rstd=rsqrtf(fmaf(s2,1.f/128.f,-m*m)+1e-5f);
    float4 gg=((const float4*)gq)[l], bb=((const float4*)bq)[l];
    float4 z4;
    z4.x=fmaf((y4.x-m)*rstd,gg.x,bb.x); z4.y=fmaf((y4.y-m)*rstd,gg.y,bb.y);
    z4.z=fmaf((y4.z-m)*rstd,gg.z,bb.z); z4.w=fmaf((y4.w-m)*rstd,gg.w,bb.w);
    ((float4*)sz[w])[l]=z4;
}

template<int NR>
static __device__ __forceinline__ void qkproj(const float (*sz)[128], float (*qkraw)[128],
        const float* gkv, const float* bkv, int qbase, int t, int w, int l){
    const int RG=NR/2;
    int c=t&127, rq=(t>>7)*RG;
    float acc[RG];
#pragma unroll
    for(int k=0;k<RG;k++) acc[k]=0.f;
    for(int e=0;e<128;e++){
        float mv=g_M1[e*128+c];
#pragma unroll
        for(int k=0;k<RG;k++) acc[k]=fmaf(sz[rq+k][e],mv,acc[k]);
    }
#pragma unroll
    for(int k=0;k<RG;k++) qkraw[rq+k][c]=acc[k];
    __syncthreads();
    if(w<NR){
        float4 qr=((const float4*)qkraw[w])[l];
        float4 g4=((const float4*)gkv)[l], b4=((const float4*)bkv)[l];
        float c1=dot4(qr,g4), c0=dot4(qr,b4);
#pragma unroll
        for(int d=16;d>0;d>>=1){c1+=__shfl_xor_sync(FULL,c1,d);c0+=__shfl_xor_sync(FULL,c0,d);}
        if(l==0){g_cq1[qbase+w]=c1; g_cq0[qbase+w]=c0;}
        float4 o; o.x=qr.x*g4.x; o.y=qr.y*g4.y; o.z=qr.z*g4.z; o.w=qr.w*g4.w;
        ((float4*)(g_qkg+(qbase+w)*128))[l]=o;
    }
}

__global__ void __launch_bounds__(256) kqk0(const float* __restrict__ gq,
        const float* __restrict__ bq, const float* __restrict__ gkv,
        const float* __restrict__ bkv){
    int qbase=blockIdx.x*8, t=threadIdx.x, w=t>>5, l=t&31;
    __shared__ float sq[8][128], sz[8][128], qkraw[8][128];
#pragma unroll
    for(int k=0;k<4;k++) ((float*)sq)[k*256+t]=g_qstate[qbase*128+k*256+t];
    __syncthreads();
    ln_row(sq,sz,gq,bq,w,l);
    __syncthreads();
    qkproj<8>(sz,qkraw,gkv,bkv,qbase,t,w,l);
}

// smem float offsets for kstream6
#define STG0 0
#define QKF  16384
#define WBUF 18432
#define RSTD 20608
#define MS   21120
#define SBLK 21632
#define T1S  23680
#define T2S  23696
#define CQ1S 23712
#define CQ0S 23728
#define SMEMF 23744

// ---- single-pass stream: grid(8,32), 256 thr, both GEMMs on tensor cores ----
__global__ void __launch_bounds__(256,2) kstream6(const float* __restrict__ inp,
        float* __restrict__ a0out, int writeA0, int iter0){
    extern __shared__ float sm[];
    int p=blockIdx.x, b=blockIdx.y, t=threadIdx.x, w=t>>5, l=t&31;
    int g=l>>2, c4=l&3;
    if(t<16){
        sm[T1S+t]=0.f; sm[T2S+t]=0.f;
        sm[CQ1S+t]=g_cq1[b*16+t]; sm[CQ0S+t]=g_cq0[b*16+t];
    }
    // phase-1 B fragments (tf32 qkg), validated R8 layout
#pragma unroll
    for(int e=0;e<8;e++){
        int gi=e*256+t;
        int j=gi&1, lane=(gi>>1)&31, kn=gi>>6;
        int k=kn>>1, nt=kn&1;
        int slot=nt*8+(lane>>2), ch=k*8+(lane&3)+j*4;
        sm[QKF+gi]=__uint_as_float(tf32r(g_qkg[b*2048+slot*128+ch]));
    }
    if(!iter0){
#pragma unroll
        for(int k=0;k<2;k++){
            sm[RSTD+k*256+t]=g_rstdc[b*4096+p*512+k*256+t];
            sm[MS+k*256+t]=g_mc[b*4096+p*512+k*256+t];
        }
    }
    __syncthreads();
    int rb=w*64;
    if(iter0){
        const float4* base=(const float4*)(inp+((size_t)b*4096+p*512+rb)*128);
        for(int i=0;i<64;i++){
            float4 x=base[i*32+l];
            float s=x.x+x.y+x.z+x.w;
            float s2=fmaf(x.x,x.x,fmaf(x.y,x.y,fmaf(x.z,x.z,x.w*x.w)));
#pragma unroll
            for(int d=16;d>0;d>>=1){s+=__shfl_xor_sync(FULL,s,d);s2+=__shfl_xor_sync(FULL,s2,d);}
            float m=s*(1.f/128.f);
            float rs=rsqrtf(fmaf(s2,1.f/128.f,-m*m)+1e-5f);
            if(l==0){sm[RSTD+rb+i]=rs;sm[MS+rb+i]=m;}
        }
        __syncthreads();
#pragma unroll
        for(int k=0;k<2;k++){
            g_rstdc[b*4096+p*512+k*256+t]=sm[RSTD+k*256+t];
            g_mc[b*4096+p*512+k*256+t]=sm[MS+k*256+t];
        }
    }
    // this thread's 4 slot positions: 2c4, 2c4+1, 2c4+8, 2c4+9
    float cq1v[4], cq0v[4];
    {
        int s0=2*c4;
        cq1v[0]=sm[CQ1S+s0];   cq1v[1]=sm[CQ1S+s0+1];
        cq1v[2]=sm[CQ1S+s0+8]; cq1v[3]=sm[CQ1S+s0+9];
        cq0v[0]=sm[CQ0S+s0];   cq0v[1]=sm[CQ0S+s0+1];
        cq0v[2]=sm[CQ0S+s0+8]; cq0v[3]=sm[CQ0S+s0+9];
    }
    float sacc[64];
#pragma unroll
    for(int i=0;i<64;i++) sacc[i]=0.f;
    float t1p[4]={0,0,0,0}, t2p[4]={0,0,0,0};
    int wst=STG0+w*2048;
    int wb=WBUF+w*272;

    for(int tile=0;tile<4;tile++){
        __syncwarp();
        int rb16=rb+tile*16;
        const float4* gsrc=(const float4*)(inp+((size_t)b*4096+p*512+rb16)*128);
        // stage full 16x128 tile (tf32, swizzled, two 64-ch halves)
#pragma unroll
        for(int half=0;half<2;half++){
#pragma unroll
            for(int ii=0;ii<8;ii++){
                int row=ii*2+(l>>4);
                float4 x=gsrc[row*32+half*16+(l&15)];
                uint4 xv;
                xv.x=tf32r(x.x); xv.y=tf32r(x.y); xv.z=tf32r(x.z); xv.w=tf32r(x.w);
                int off=wst+half*1024+row*64+(((l&15)*4)^((row&7)<<2));
                *(uint4*)(sm+off)=xv;
            }
        }
        __syncwarp();
        // phase 1: logits MMA (M=row, N=slot)
        float d0[4]={0,0,0,0}, d1[4]={0,0,0,0};
        int abase=wst+g*64;
#pragma unroll
        for(int k=0;k<16;k++){
            int half=k>>3, kk=k&7;
            int ab=abase+half*1024;
            int x0=((kk*8)+c4)^(g<<2);
            unsigned a0=__float_as_uint(sm[ab+x0]);
            unsigned a1=__float_as_uint(sm[ab+512+x0]);
            unsigned a2=__float_as_uint(sm[ab+(x0^4)]);
            unsigned a3=__float_as_uint(sm[ab+512+(x0^4)]);
            float2 bb=*(const float2*)&sm[QKF+(k*2+0)*64+l*2];
            MMA1688(d0,a0,a1,a2,a3,__float_as_uint(bb.x),__float_as_uint(bb.y));
            float2 bc=*(const float2*)&sm[QKF+(k*2+1)*64+l*2];
            MMA1688(d1,a0,a1,a2,a3,__float_as_uint(bc.x),__float_as_uint(bc.y));
        }
        // logits adjust + softmax (rows g and g+8)
        int r0g=rb16+g, r1g=r0g+8;
        float rs0=sm[RSTD+r0g], m0=sm[MS+r0g];
        float rs1=sm[RSTD+r1g], m1=sm[MS+r1g];
        float Lg[4], Lh[4];
        Lg[0]=fmaf(rs0,fmaf(-m0,cq1v[0],d0[0]),cq0v[0]);
        Lg[1]=fmaf(rs0,fmaf(-m0,cq1v[1],d0[1]),cq0v[1]);
        Lg[2]=fmaf(rs0,fmaf(-m0,cq1v[2],d1[0]),cq0v[2]);
        Lg[3]=fmaf(rs0,fmaf(-m0,cq1v[3],d1[1]),cq0v[3]);
        Lh[0]=fmaf(rs1,fmaf(-m1,cq1v[0],d0[2]),cq0v[0]);
        Lh[1]=fmaf(rs1,fmaf(-m1,cq1v[1],d0[3]),cq0v[1]);
        Lh[2]=fmaf(rs1,fmaf(-m1,cq1v[2],d1[2]),cq0v[2]);
        Lh[3]=fmaf(rs1,fmaf(-m1,cq1v[3],d1[3]),cq0v[3]);
        float mx0=fmaxf(fmaxf(Lg[0],Lg[1]),fmaxf(Lg[2],Lg[3]));
        float mx1=fmaxf(fmaxf(Lh[0],Lh[1]),fmaxf(Lh[2],Lh[3]));
        mx0=fmaxf(mx0,__shfl_xor_sync(FULL,mx0,1));
        mx0=fmaxf(mx0,__shfl_xor_sync(FULL,mx0,2));
        mx1=fmaxf(mx1,__shfl_xor_sync(FULL,mx1,1));
        mx1=fmaxf(mx1,__shfl_xor_sync(FULL,mx1,2));
        float ag[4], ah[4], sum0=0.f, sum1=0.f;
#pragma unroll
        for(int j=0;j<4;j++){
            ag[j]=fexp(Lg[j]-mx0); sum0+=ag[j];
            ah[j]=fexp(Lh[j]-mx1); sum1+=ah[j];
        }
        sum0+=__shfl_xor_sync(FULL,sum0,1); sum0+=__shfl_xor_sync(FULL,sum0,2);
        sum1+=__shfl_xor_sync(FULL,sum1,1); sum1+=__shfl_xor_sync(FULL,sum1,2);
        float inv0=1.f/sum0, inv1=1.f/sum1;
        float rm0=rs0*m0, rm1=rs1*m1;
#pragma unroll
        for(int j=0;j<4;j++){
            ag[j]*=inv0; ah[j]*=inv1;
            t2p[j]+=ag[j]+ah[j];
            t1p[j]+=ag[j]*rm0+ah[j]*rm1;
        }
        // write a0 to wbuf[row][slot] (stride 17)
        {
            int s0=2*c4;
            sm[wb+g*17+s0]=ag[0];     sm[wb+g*17+s0+1]=ag[1];
            sm[wb+g*17+s0+8]=ag[2];   sm[wb+g*17+s0+9]=ag[3];
            sm[wb+(g+8)*17+s0]=ah[0]; sm[wb+(g+8)*17+s0+1]=ah[1];
            sm[wb+(g+8)*17+s0+8]=ah[2]; sm[wb+(g+8)*17+s0+9]=ah[3];
        }
        __syncwarp();
        if(writeA0){
            int row=l&15, sh=l>>4;
#pragma unroll
            for(int j=0;j<8;j++){
                int slot=j*2+sh;
                a0out[(size_t)b*65536+(size_t)slot*4096+p*512+rb16+row]=sm[wb+row*17+slot];
            }
        }
        // phase 3: S += w^T @ x  (M=slot, K=row, N=ch)
#pragma unroll
        for(int kc=0;kc<2;kc++){
            int ra=kc*8+c4, rb2=ra+4;
            float rsa=sm[RSTD+rb16+ra], rsb=sm[RSTD+rb16+rb2];
            unsigned A0=tf32r(sm[wb+ra*17+g]*rsa);
            unsigned A1=tf32r(sm[wb+ra*17+g+8]*rsa);
            unsigned A2=tf32r(sm[wb+rb2*17+g]*rsb);
            unsigned A3=tf32r(sm[wb+rb2*17+g+8]*rsb);
            int swa=(c4<<2), swb=((c4+4)<<2);
#pragma unroll
            for(int nt=0;nt<16;nt++){
                int half=nt>>3;
                int chh=(nt&7)*8+g;
                int c16=chh>>2, frac=chh&3;
                unsigned B0=__float_as_uint(sm[wst+half*1024+ra*64+(((c16*4)^swa)+frac)]);
                unsigned B1=__float_as_uint(sm[wst+half*1024+rb2*64+(((c16*4)^swb)+frac)]);
                MMA1688((&sacc[nt*4]),A0,A1,A2,A3,B0,B1);
            }
        }
    }
    // t1/t2 reduce over g lanes (stride-4 lanes share c4)
#pragma unroll
    for(int j=0;j<4;j++){
#pragma unroll
        for(int d=4;d<32;d<<=1){
            t2p[j]+=__shfl_xor_sync(FULL,t2p[j],d);
            t1p[j]+=__shfl_xor_sync(FULL,t1p[j],d);
        }
    }
    if(l<4){
        int s0=2*l;
        atomicAdd(&sm[T2S+s0],t2p[0]);   atomicAdd(&sm[T2S+s0+1],t2p[1]);
        atomicAdd(&sm[T2S+s0+8],t2p[2]); atomicAdd(&sm[T2S+s0+9],t2p[3]);
        atomicAdd(&sm[T1S+s0],t1p[0]);   atomicAdd(&sm[T1S+s0+1],t1p[1]);
        atomicAdd(&sm[T1S+s0+8],t1p[2]); atomicAdd(&sm[T1S+s0+9],t1p[3]);
    }
    __syncthreads();
    for(int i=t;i<2048;i+=256) sm[SBLK+i]=0.f;
    __syncthreads();
#pragma unroll
    for(int nt=0;nt<16;nt++){
        int ch0=nt*8+2*c4;
        atomicAdd(&sm[SBLK+g*128+ch0],sacc[nt*4+0]);
        atomicAdd(&sm[SBLK+g*128+ch0+1],sacc[nt*4+1]);
        atomicAdd(&sm[SBLK+(g+8)*128+ch0],sacc[nt*4+2]);
        atomicAdd(&sm[SBLK+(g+8)*128+ch0+1],sacc[nt*4+3]);
    }
    __syncthreads();
    float* tp=g_Tpart+((size_t)(b*8+p))*2048;
    for(int i=t;i<2048;i+=256) tp[i]=sm[SBLK+i];
    if(t<16){g_t1p[(b*8+p)*16+t]=sm[T1S+t];g_t2p[(b*8+p)*16+t]=sm[T2S+t];}
}

// ---- fused tail: unchanged R8 ----
__global__ void __launch_bounds__(256) ktail(const float* __restrict__ Wv,
        const float* __restrict__ gkv, const float* __restrict__ bkv,
        const float* __restrict__ wih, const float* __restrict__ whh,
        const float* __restrict__ bih, const float* __restrict__ bhh,
        const float* __restrict__ g2, const float* __restrict__ b2ln,
        const float* __restrict__ w1, const float* __restrict__ b1,
        const float* __restrict__ w2, const float* __restrict__ b2f,
        const float* __restrict__ gq, const float* __restrict__ bq,
        float* __restrict__ qout, int last){
    int blk=blockIdx.x, b=blk>>2, qh=(blk&3)*4;
    int t=threadIdx.x, w=t>>5, l=t&31;
    __shared__ float Sh[4][128], su[4][128], sx[4][128], sy[4][128], sh1[4][512];
    __shared__ float t1a[4], t2a[4], rsa[4];
    if(t<4){
        float s1=0.f,s2=0.f;
        for(int p=0;p<8;p++){
            s1+=g_t1p[(b*8+p)*16+qh+t];
            s2+=g_t2p[(b*8+p)*16+qh+t];
        }
        t1a[t]=s1; t2a[t]=s2; rsa[t]=1.f/(s2+1e-5f);
    }
#pragma unroll
    for(int k=0;k<2;k++)
        ((float*)sx)[k*256+t]=g_qstate[(b*16+qh)*128+k*256+t];
    __syncthreads();
#pragma unroll
    for(int k=0;k<2;k++){
        int idx=k*256+t, q=idx>>7, c=idx&127;
        float a=0.f;
        for(int p=0;p<8;p++) a+=g_Tpart[((size_t)(b*8+p))*2048+(qh+q)*128+c];
        ((float*)Sh)[idx]=fmaf(gkv[c],a-t1a[q],bkv[c]*t2a[q]);
    }
    __syncthreads();
    {
        int c=t&127, qg=(t>>7)*2;
        float acc0=0.f, acc1=0.f;
        const float4* wr=(const float4*)(Wv+(size_t)c*128);
        for(int d=0;d<32;d++){
            float4 wv=wr[d];
            acc0+=dot4(((const float4*)Sh[qg])[d],wv);
            acc1+=dot4(((const float4*)Sh[qg+1])[d],wv);
        }
        su[qg][c]=acc0*rsa[qg];
        su[qg+1][c]=acc1*rsa[qg+1];
    }
    __syncthreads();
    {
        int c=t&127, rh=(t>>7)*2;
        float aIR[2]={0,0},aIZ[2]={0,0},aIN[2]={0,0};
        float aHR[2]={0,0},aHZ[2]={0,0},aHN[2]={0,0};
        const float4* wir=(const float4*)(wih+(size_t)c*128);
        const float4* wiz=(const float4*)(wih+(size_t)(c+128)*128);
        const float4* win=(const float4*)(wih+(size_t)(c+256)*128);
        const float4* whr=(const float4*)(whh+(size_t)c*128);
        const float4* whz=(const float4*)(whh+(size_t)(c+128)*128);
        const float4* whn=(const float4*)(whh+(size_t)(c+256)*128);
        for(int d=0;d<32;d++){
            float4 w0=wir[d],w1_=wiz[d],w2_=win[d],w3=whr[d],w4=whz[d],w5=whn[d];
#pragma unroll
            for(int k=0;k<2;k++){
                float4 u4=((const float4*)su[rh+k])[d], x4=((const float4*)sx[rh+k])[d];
                aIR[k]+=dot4(u4,w0); aIZ[k]+=dot4(u4,w1_); aIN[k]+=dot4(u4,w2_);
                aHR[k]+=dot4(x4,w3); aHZ[k]+=dot4(x4,w4); aHN[k]+=dot4(x4,w5);
            }
        }
        float bir=bih[c],biz=bih[c+128],bin=bih[c+256];
        float bhr=bhh[c],bhz=bhh[c+128],bhn=bhh[c+256];
#pragma unroll
        for(int k=0;k<2;k++){
            float rr=1.f/(1.f+fexp(-(aIR[k]+bir+aHR[k]+bhr)));
            float zz=1.f/(1.f+fexp(-(aIZ[k]+biz+aHZ[k]+bhz)));
            float nn=tanhf(aIN[k]+bin+rr*(aHN[k]+bhn));
            sy[rh+k][c]=(1.f-zz)*nn+zz*sx[rh+k][c];
        }
    }
    __syncthreads();
    if(w<4) ln_row(sy,Sh,g2,b2ln,w,l);
    __syncthreads();
    {
        float acc0[4]={0,0,0,0}, acc1[4]={0,0,0,0};
        const float4* wa=(const float4*)(w1+(size_t)t*128);
        const float4* wb=(const float4*)(w1+(size_t)(t+256)*128);
        for(int d=0;d<32;d++){
            float4 a=wa[d], bb=wb[d];
#pragma unroll
            for(int r=0;r<4;r++){
                float4 zz=((const float4*)Sh[r])[d];
                acc0[r]+=dot4(zz,a); acc1[r]+=dot4(zz,bb);
            }
        }
        float b0=b1[t], b256=b1[t+256];
#pragma unroll
        for(int r=0;r<4;r++){
            sh1[r][t]=fmaxf(acc0[r]+b0,0.f);
            sh1[r][t+256]=fmaxf(acc1[r]+b256,0.f);
        }
    }
    __syncthreads();
    {
        int c=t&127, rh=(t>>7)*2;
        float acc0=0.f, acc1=0.f;
        const float4* wp=(const float4*)(w2+(size_t)c*512);
        for(int d=0;d<128;d++){
            float4 wv=wp[d];
            acc0+=dot4(((const float4*)sh1[rh])[d],wv);
            acc1+=dot4(((const float4*)sh1[rh+1])[d],wv);
        }
        float bb=b2f[c];
        float v0=sy[rh][c]+acc0+bb;
        float v1=sy[rh+1][c]+acc1+bb;
        g_qstate[(b*16+qh+rh)*128+c]=v0;
        g_qstate[(b*16+qh+rh+1)*128+c]=v1;
        su[rh][c]=v0; su[rh+1][c]=v1;
        if(last){
            qout[(b*16+qh+rh)*128+c]=v0;
            qout[(b*16+qh+rh+1)*128+c]=v1;
        }
    }
    __syncthreads();
    if(last) return;
    if(w<4) ln_row(su,sy,gq,bq,w,l);
    __syncthreads();
    qkproj<4>(sy,Sh,gkv,bkv,b*16+qh,t,w,l);
}

extern "C" void kernel_launch(void* const* d_in, const int* in_sizes, int n_in,
                              void* d_out, int out_size){
    const float* inp=(const float*)d_in[0];
    const float* query=(const float*)d_in[1];
    const float* ln_kv_g=(const float*)d_in[2];
    const float* ln_kv_b=(const float*)d_in[3];
    const float* Wk=(const float*)d_in[4];
    const float* Wv=(const float*)d_in[5];
    const float* ln_q_g=(const float*)d_in[6];
    const float* ln_q_b=(const float*)d_in[7];
    const float* Wq=(const float*)d_in[8];
    const float* gru_wih=(const float*)d_in[9];
    const float* gru_whh=(const float*)d_in[10];
    const float* gru_bih=(const float*)d_in[11];
    const float* gru_bhh=(const float*)d_in[12];
    const float* ln2_g=(const float*)d_in[13];
    const float* ln2_b=(const float*)d_in[14];
    const float* ffn_w1=(const float*)d_in[15];
    const float* ffn_b1=(const float*)d_in[16];
    const float* ffn_w2=(const float*)d_in[17];
    const float* ffn_b2=(const float*)d_in[18];
    float* out=(float*)d_out;
    float* a0out=out+32*16*128;

    int smemB = SMEMF*4;
    cudaFuncSetAttribute(kstream6, cudaFuncAttributeMaxDynamicSharedMemorySize, smemB);
    kM1<<<128,128>>>(Wq,Wk);
    kcopy<<<512,128>>>(query);
    kqk0<<<64,256>>>(ln_q_g,ln_q_b,ln_kv_g,ln_kv_b);
    for(int it=0;it<3;it++){
        int last=(it==2);
        kstream6<<<dim3(8,32),256,smemB>>>(inp,a0out,last,it==0);
        ktail<<<128,256>>>(Wv,ln_kv_g,ln_kv_b,gru_wih,gru_whh,gru_bih,gru_bhh,
                           ln2_g,ln2_b,ffn_w1,ffn_b1,ffn_w2,ffn_b2,
                           ln_q_g,ln_q_b,out,last);
    }
}

// round 10
// speedup vs baseline: 2.2081x; 1.2618x over previous
#include <cuda_runtime.h>
#include <math.h>
#define FULL 0xffffffffu

__device__ float g_M1[128*128];
__device__ float g_qstate[32*16*128];
__device__ float g_qkg[32*16*128];
__device__ float g_cq1[32*16];
__device__ float g_cq0[32*16];
__device__ float g_Tpart[32*8*16*128];
__device__ float g_t1p[32*8*16];
__device__ float g_t2p[32*8*16];
__device__ float g_rstdc[32*4096];
__device__ float g_mc[32*4096];

static __device__ __forceinline__ float dot4(float4 a, float4 b) {
    return fmaf(a.x,b.x,fmaf(a.y,b.y,fmaf(a.z,b.z,a.w*b.w)));
}
static __device__ __forceinline__ unsigned tf32r(float x){
    unsigned u; asm("cvt.rna.tf32.f32 %0, %1;" : "=r"(u) : "f"(x)); return u;
}
#define MMA1688(D,A0,A1,A2,A3,B0,B1) \
  asm volatile("mma.sync.aligned.m16n8k8.row.col.f32.tf32.tf32.f32 " \
    "{%0,%1,%2,%3},{%4,%5,%6,%7},{%8,%9},{%0,%1,%2,%3};" \
    : "+f"(D[0]),"+f"(D[1]),"+f"(D[2]),"+f"(D[3]) \
    : "r"(A0),"r"(A1),"r"(A2),"r"(A3),"r"(B0),"r"(B1))

static __device__ __forceinline__ float fexp(float x) {
    x = fmaxf(x, -87.f);
    float t = fmaf(x, 1.4426950408889634f, 12582912.f);
    int ni = __float_as_int(t) - 0x4B400000;
    float n = t - 12582912.f;
    float f = fmaf(x, 1.4426950408889634f, -n);
    float p = 1.5403530e-4f;
    p = fmaf(p,f,1.3333558e-3f); p = fmaf(p,f,9.6181291e-3f);
    p = fmaf(p,f,5.5504109e-2f); p = fmaf(p,f,2.4022651e-1f);
    p = fmaf(p,f,6.9314718e-1f); p = fmaf(p,f,1.f);
    return p * __int_as_float((ni + 127) << 23);
}

__global__ void kcopy(const float* __restrict__ s){
    int i = blockIdx.x*128+threadIdx.x; g_qstate[i]=s[i];
}
__global__ void kM1(const float* __restrict__ Wq, const float* __restrict__ Wk){
    int e=blockIdx.x, d=threadIdx.x; float a=0.f;
    for(int c=0;c<128;c++) a=fmaf(Wq[c*128+e],Wk[c*128+d],a);
    g_M1[e*128+d]=a*0.08838834764831845f;
}

static __device__ __forceinline__ void ln_row(const float (*sq)[128], float (*sz)[128],
        const float* gq, const float* bq, int w, int l){
    float4 y4=((const float4*)sq[w])[l];
    float s=y4.x+y4.y+y4.z+y4.w;
    float s2=fmaf(y4.x,y4.x,fmaf(y4.y,y4.y,fmaf(y4.z,y4.z,y4.w*y4.w)));
#pragma unroll
    for(int d=16;d>0;d>>=1){s+=__shfl_xor_sync(FULL,s,d);s2+=__shfl_xor_sync(FULL,s2,d);}
    float m=s*(1.f/128.f);
    float rstd=rsqrtf(fmaf(s2,1.f/128.f,-m*m)+1e-5f);
    float4 gg=((const float4*)gq)[l], bb=((const float4*)bq)[l];
    float4 z4;
    z4.x=fmaf((y4.x-m)*rstd,gg.x,bb.x); z4.y=fmaf((y4.y-m)*rstd,gg.y,bb.y);
    z4.z=fmaf((y4.z-m)*rstd,gg.z,bb.z); z4.w=fmaf((y4.w-m)*rstd,gg.w,bb.w);
    ((float4*)sz[w])[l]=z4;
}

template<int NR>
static __device__ __forceinline__ void qkproj(const float (*sz)[128], float (*qkraw)[128],
        const float* gkv, const float* bkv, int qbase, int t, int w, int l){
    const int RG=NR/2;
    int c=t&127, rq=(t>>7)*RG;
    float acc[RG];
#pragma unroll
    for(int k=0;k<RG;k++) acc[k]=0.f;
    for(int e=0;e<128;e++){
        float mv=g_M1[e*128+c];
#pragma unroll
        for(int k=0;k<RG;k++) acc[k]=fmaf(sz[rq+k][e],mv,acc[k]);
    }
#pragma unroll
    for(int k=0;k<RG;k++) qkraw[rq+k][c]=acc[k];
    __syncthreads();
    if(w<NR){
        float4 qr=((const float4*)qkraw[w])[l];
        float4 g4=((const float4*)gkv)[l], b4=((const float4*)bkv)[l];
        float c1=dot4(qr,g4), c0=dot4(qr,b4);
#pragma unroll
        for(int d=16;d>0;d>>=1){c1+=__shfl_xor_sync(FULL,c1,d);c0+=__shfl_xor_sync(FULL,c0,d);}
        if(l==0){g_cq1[qbase+w]=c1; g_cq0[qbase+w]=c0;}
        float4 o; o.x=qr.x*g4.x; o.y=qr.y*g4.y; o.z=qr.z*g4.z; o.w=qr.w*g4.w;
        ((float4*)(g_qkg+(qbase+w)*128))[l]=o;
    }
}

__global__ void __launch_bounds__(256) kqk0(const float* __restrict__ gq,
        const float* __restrict__ bq, const float* __restrict__ gkv,
        const float* __restrict__ bkv){
    int qbase=blockIdx.x*8, t=threadIdx.x, w=t>>5, l=t&31;
    __shared__ float sq[8][128], sz[8][128], qkraw[8][128];
#pragma unroll
    for(int k=0;k<4;k++) ((float*)sq)[k*256+t]=g_qstate[qbase*128+k*256+t];
    __syncthreads();
    ln_row(sq,sz,gq,bq,w,l);
    __syncthreads();
    qkproj<8>(sz,qkraw,gkv,bkv,qbase,t,w,l);
}

// smem float offsets for kstream6
#define STG0 0
#define QKF  16384
#define WBUF 18432
#define RSTD 20608
#define MS   21120
#define SBLK 21632
#define T1S  23680
#define T2S  23696
#define CQ1S 23712
#define CQ0S 23728
#define SMEMF 23744

// ---- single-pass stream (unchanged R9) ----
__global__ void __launch_bounds__(256,2) kstream6(const float* __restrict__ inp,
        float* __restrict__ a0out, int writeA0, int iter0){
    extern __shared__ float sm[];
    int p=blockIdx.x, b=blockIdx.y, t=threadIdx.x, w=t>>5, l=t&31;
    int g=l>>2, c4=l&3;
    if(t<16){
        sm[T1S+t]=0.f; sm[T2S+t]=0.f;
        sm[CQ1S+t]=g_cq1[b*16+t]; sm[CQ0S+t]=g_cq0[b*16+t];
    }
#pragma unroll
    for(int e=0;e<8;e++){
        int gi=e*256+t;
        int j=gi&1, lane=(gi>>1)&31, kn=gi>>6;
        int k=kn>>1, nt=kn&1;
        int slot=nt*8+(lane>>2), ch=k*8+(lane&3)+j*4;
        sm[QKF+gi]=__uint_as_float(tf32r(g_qkg[b*2048+slot*128+ch]));
    }
    if(!iter0){
#pragma unroll
        for(int k=0;k<2;k++){
            sm[RSTD+k*256+t]=g_rstdc[b*4096+p*512+k*256+t];
            sm[MS+k*256+t]=g_mc[b*4096+p*512+k*256+t];
        }
    }
    __syncthreads();
    int rb=w*64;
    if(iter0){
        const float4* base=(const float4*)(inp+((size_t)b*4096+p*512+rb)*128);
        for(int i=0;i<64;i++){
            float4 x=base[i*32+l];
            float s=x.x+x.y+x.z+x.w;
            float s2=fmaf(x.x,x.x,fmaf(x.y,x.y,fmaf(x.z,x.z,x.w*x.w)));
#pragma unroll
            for(int d=16;d>0;d>>=1){s+=__shfl_xor_sync(FULL,s,d);s2+=__shfl_xor_sync(FULL,s2,d);}
            float m=s*(1.f/128.f);
            float rs=rsqrtf(fmaf(s2,1.f/128.f,-m*m)+1e-5f);
            if(l==0){sm[RSTD+rb+i]=rs;sm[MS+rb+i]=m;}
        }
        __syncthreads();
#pragma unroll
        for(int k=0;k<2;k++){
            g_rstdc[b*4096+p*512+k*256+t]=sm[RSTD+k*256+t];
            g_mc[b*4096+p*512+k*256+t]=sm[MS+k*256+t];
        }
    }
    float cq1v[4], cq0v[4];
    {
        int s0=2*c4;
        cq1v[0]=sm[CQ1S+s0];   cq1v[1]=sm[CQ1S+s0+1];
        cq1v[2]=sm[CQ1S+s0+8]; cq1v[3]=sm[CQ1S+s0+9];
        cq0v[0]=sm[CQ0S+s0];   cq0v[1]=sm[CQ0S+s0+1];
        cq0v[2]=sm[CQ0S+s0+8]; cq0v[3]=sm[CQ0S+s0+9];
    }
    float sacc[64];
#pragma unroll
    for(int i=0;i<64;i++) sacc[i]=0.f;
    float t1p[4]={0,0,0,0}, t2p[4]={0,0,0,0};
    int wst=STG0+w*2048;
    int wb=WBUF+w*272;

    for(int tile=0;tile<4;tile++){
        __syncwarp();
        int rb16=rb+tile*16;
        const float4* gsrc=(const float4*)(inp+((size_t)b*4096+p*512+rb16)*128);
#pragma unroll
        for(int half=0;half<2;half++){
#pragma unroll
            for(int ii=0;ii<8;ii++){
                int row=ii*2+(l>>4);
                float4 x=gsrc[row*32+half*16+(l&15)];
                uint4 xv;
                xv.x=tf32r(x.x); xv.y=tf32r(x.y); xv.z=tf32r(x.z); xv.w=tf32r(x.w);
                int off=wst+half*1024+row*64+(((l&15)*4)^((row&7)<<2));
                *(uint4*)(sm+off)=xv;
            }
        }
        __syncwarp();
        float d0[4]={0,0,0,0}, d1[4]={0,0,0,0};
        int abase=wst+g*64;
#pragma unroll
        for(int k=0;k<16;k++){
            int half=k>>3, kk=k&7;
            int ab=abase+half*1024;
            int x0=((kk*8)+c4)^(g<<2);
            unsigned a0=__float_as_uint(sm[ab+x0]);
            unsigned a1=__float_as_uint(sm[ab+512+x0]);
            unsigned a2=__float_as_uint(sm[ab+(x0^4)]);
            unsigned a3=__float_as_uint(sm[ab+512+(x0^4)]);
            float2 bb=*(const float2*)&sm[QKF+(k*2+0)*64+l*2];
            MMA1688(d0,a0,a1,a2,a3,__float_as_uint(bb.x),__float_as_uint(bb.y));
            float2 bc=*(const float2*)&sm[QKF+(k*2+1)*64+l*2];
            MMA1688(d1,a0,a1,a2,a3,__float_as_uint(bc.x),__float_as_uint(bc.y));
        }
        int r0g=rb16+g, r1g=r0g+8;
        float rs0=sm[RSTD+r0g], m0=sm[MS+r0g];
        float rs1=sm[RSTD+r1g], m1=sm[MS+r1g];
        float Lg[4], Lh[4];
        Lg[0]=fmaf(rs0,fmaf(-m0,cq1v[0],d0[0]),cq0v[0]);
        Lg[1]=fmaf(rs0,fmaf(-m0,cq1v[1],d0[1]),cq0v[1]);
        Lg[2]=fmaf(rs0,fmaf(-m0,cq1v[2],d1[0]),cq0v[2]);
        Lg[3]=fmaf(rs0,fmaf(-m0,cq1v[3],d1[1]),cq0v[3]);
        Lh[0]=fmaf(rs1,fmaf(-m1,cq1v[0],d0[2]),cq0v[0]);
        Lh[1]=fmaf(rs1,fmaf(-m1,cq1v[1],d0[3]),cq0v[1]);
        Lh[2]=fmaf(rs1,fmaf(-m1,cq1v[2],d1[2]),cq0v[2]);
        Lh[3]=fmaf(rs1,fmaf(-m1,cq1v[3],d1[3]),cq0v[3]);
        float mx0=fmaxf(fmaxf(Lg[0],Lg[1]),fmaxf(Lg[2],Lg[3]));
        float mx1=fmaxf(fmaxf(Lh[0],Lh[1]),fmaxf(Lh[2],Lh[3]));
        mx0=fmaxf(mx0,__shfl_xor_sync(FULL,mx0,1));
        mx0=fmaxf(mx0,__shfl_xor_sync(FULL,mx0,2));
        mx1=fmaxf(mx1,__shfl_xor_sync(FULL,mx1,1));
        mx1=fmaxf(mx1,__shfl_xor_sync(FULL,mx1,2));
        float ag[4], ah[4], sum0=0.f, sum1=0.f;
#pragma unroll
        for(int j=0;j<4;j++){
            ag[j]=fexp(Lg[j]-mx0); sum0+=ag[j];
            ah[j]=fexp(Lh[j]-mx1); sum1+=ah[j];
        }
        sum0+=__shfl_xor_sync(FULL,sum0,1); sum0+=__shfl_xor_sync(FULL,sum0,2);
        sum1+=__shfl_xor_sync(FULL,sum1,1); sum1+=__shfl_xor_sync(FULL,sum1,2);
        float inv0=1.f/sum0, inv1=1.f/sum1;
        float rm0=rs0*m0, rm1=rs1*m1;
#pragma unroll
        for(int j=0;j<4;j++){
            ag[j]*=inv0; ah[j]*=inv1;
            t2p[j]+=ag[j]+ah[j];
            t1p[j]+=ag[j]*rm0+ah[j]*rm1;
        }
        {
            int s0=2*c4;
            sm[wb+g*17+s0]=ag[0];     sm[wb+g*17+s0+1]=ag[1];
            sm[wb+g*17+s0+8]=ag[2];   sm[wb+g*17+s0+9]=ag[3];
            sm[wb+(g+8)*17+s0]=ah[0]; sm[wb+(g+8)*17+s0+1]=ah[1];
            sm[wb+(g+8)*17+s0+8]=ah[2]; sm[wb+(g+8)*17+s0+9]=ah[3];
        }
        __syncwarp();
        if(writeA0){
            int row=l&15, sh=l>>4;
#pragma unroll
            for(int j=0;j<8;j++){
                int slot=j*2+sh;
                a0out[(size_t)b*65536+(size_t)slot*4096+p*512+rb16+row]=sm[wb+row*17+slot];
            }
        }
#pragma unroll
        for(int kc=0;kc<2;kc++){
            int ra=kc*8+c4, rb2=ra+4;
            float rsa=sm[RSTD+rb16+ra], rsb=sm[RSTD+rb16+rb2];
            unsigned A0=tf32r(sm[wb+ra*17+g]*rsa);
            unsigned A1=tf32r(sm[wb+ra*17+g+8]*rsa);
            unsigned A2=tf32r(sm[wb+rb2*17+g]*rsb);
            unsigned A3=tf32r(sm[wb+rb2*17+g+8]*rsb);
            int swa=(c4<<2), swb=((c4+4)<<2);
#pragma unroll
            for(int nt=0;nt<16;nt++){
                int half=nt>>3;
                int chh=(nt&7)*8+g;
                int c16=chh>>2, frac=chh&3;
                unsigned B0=__float_as_uint(sm[wst+half*1024+ra*64+(((c16*4)^swa)+frac)]);
                unsigned B1=__float_as_uint(sm[wst+half*1024+rb2*64+(((c16*4)^swb)+frac)]);
                MMA1688((&sacc[nt*4]),A0,A1,A2,A3,B0,B1);
            }
        }
    }
#pragma unroll
    for(int j=0;j<4;j++){
#pragma unroll
        for(int d=4;d<32;d<<=1){
            t2p[j]+=__shfl_xor_sync(FULL,t2p[j],d);
            t1p[j]+=__shfl_xor_sync(FULL,t1p[j],d);
        }
    }
    if(l<4){
        int s0=2*l;
        atomicAdd(&sm[T2S+s0],t2p[0]);   atomicAdd(&sm[T2S+s0+1],t2p[1]);
        atomicAdd(&sm[T2S+s0+8],t2p[2]); atomicAdd(&sm[T2S+s0+9],t2p[3]);
        atomicAdd(&sm[T1S+s0],t1p[0]);   atomicAdd(&sm[T1S+s0+1],t1p[1]);
        atomicAdd(&sm[T1S+s0+8],t1p[2]); atomicAdd(&sm[T1S+s0+9],t1p[3]);
    }
    __syncthreads();
    for(int i=t;i<2048;i+=256) sm[SBLK+i]=0.f;
    __syncthreads();
#pragma unroll
    for(int nt=0;nt<16;nt++){
        int ch0=nt*8+2*c4;
        atomicAdd(&sm[SBLK+g*128+ch0],sacc[nt*4+0]);
        atomicAdd(&sm[SBLK+g*128+ch0+1],sacc[nt*4+1]);
        atomicAdd(&sm[SBLK+(g+8)*128+ch0],sacc[nt*4+2]);
        atomicAdd(&sm[SBLK+(g+8)*128+ch0+1],sacc[nt*4+3]);
    }
    __syncthreads();
    float* tp=g_Tpart+((size_t)(b*8+p))*2048;
    for(int i=t;i<2048;i+=256) tp[i]=sm[SBLK+i];
    if(t<16){g_t1p[(b*8+p)*16+t]=sm[T1S+t];g_t2p[(b*8+p)*16+t]=sm[T2S+t];}
}

// ---- ktail v2: zero-dup weights + K-split. 128 blocks x 256 thr, 4 rows ----
__global__ void __launch_bounds__(256) ktail2(const float* __restrict__ Wv,
        const float* __restrict__ gkv, const float* __restrict__ bkv,
        const float* __restrict__ wih, const float* __restrict__ whh,
        const float* __restrict__ bih, const float* __restrict__ bhh,
        const float* __restrict__ g2, const float* __restrict__ b2ln,
        const float* __restrict__ w1, const float* __restrict__ b1,
        const float* __restrict__ w2, const float* __restrict__ b2f,
        const float* __restrict__ gq, const float* __restrict__ bq,
        float* __restrict__ qout, int last){
    int blk=blockIdx.x, b=blk>>2, qh=(blk&3)*4;
    int t=threadIdx.x, w=t>>5, l=t&31;
    __shared__ float Sh[4][128], su[4][128], sx[4][128], sy[4][128];
    __shared__ float gg[4][772];           // GRU gate partials (768 + pad)
    __shared__ float pu[2][4][128];        // K-split partials
    __shared__ float sh1[4][512];
    __shared__ float t1a[4], t2a[4], rsa[4];
    float (*szb)[128] = (float(*)[128])sh1;   // reuse sh1 as LN buffer pre-FFN

    if(t<4){
        float s1=0.f,s2=0.f;
        for(int p=0;p<8;p++){
            s1+=g_t1p[(b*8+p)*16+qh+t];
            s2+=g_t2p[(b*8+p)*16+qh+t];
        }
        t1a[t]=s1; t2a[t]=s2; rsa[t]=1.f/(s2+1e-5f);
    }
#pragma unroll
    for(int k=0;k<2;k++)
        ((float*)sx)[k*256+t]=g_qstate[(b*16+qh)*128+k*256+t];
    __syncthreads();
    // S reduce + kv-LN correction
#pragma unroll
    for(int k=0;k<2;k++){
        int idx=k*256+t, q=idx>>7, c=idx&127;
        float a=0.f;
        for(int p=0;p<8;p++) a+=g_Tpart[((size_t)(b*8+p))*2048+(qh+q)*128+c];
        ((float*)Sh)[idx]=fmaf(gkv[c],a-t1a[q],bkv[c]*t2a[q]);
    }
    __syncthreads();
    // u-proj: thread (c, K-half h). Wv row c read once per block.
    {
        int c=t&127, h=t>>7;
        float acc[4]={0,0,0,0};
        const float4* wr=(const float4*)(Wv+(size_t)c*128+h*64);
        for(int d=0;d<16;d++){
            float4 wv=wr[d];
#pragma unroll
            for(int k=0;k<4;k++) acc[k]+=dot4(((const float4*)(Sh[k]+h*64))[d],wv);
        }
#pragma unroll
        for(int k=0;k<4;k++) pu[h][k][c]=acc[k];
    }
    __syncthreads();
#pragma unroll
    for(int j=0;j<2;j++){
        int i=t+j*256, r=i>>7, c=i&127;
        su[r][c]=(pu[0][r][c]+pu[1][r][c])*rsa[r];
    }
    __syncthreads();
    // GRU gates: 768 GEMVs, each weight row read once. o = t, t+256, t+512.
#pragma unroll
    for(int j=0;j<3;j++){
        int o=t+j*256;
        const float* wrow = (o<384) ? (wih+(size_t)o*128) : (whh+(size_t)(o-384)*128);
        const float (*A)[128] = (o<384) ? su : sx;
        const float4* wr=(const float4*)wrow;
        float acc[4]={0,0,0,0};
        for(int d=0;d<32;d++){
            float4 wv=wr[d];
#pragma unroll
            for(int k=0;k<4;k++) acc[k]+=dot4(((const float4*)A[k])[d],wv);
        }
#pragma unroll
        for(int k=0;k<4;k++) gg[k][o]=acc[k];
    }
    __syncthreads();
    // GRU recombine -> sy
#pragma unroll
    for(int j=0;j<2;j++){
        int i=t+j*256, r=i>>7, c=i&127;
        float rr=1.f/(1.f+fexp(-(gg[r][c]+bih[c]+gg[r][384+c]+bhh[c])));
        float zz=1.f/(1.f+fexp(-(gg[r][128+c]+bih[128+c]+gg[r][512+c]+bhh[128+c])));
        float nn=tanhf(gg[r][256+c]+bih[256+c]+rr*(gg[r][640+c]+bhh[256+c]));
        sy[r][c]=(1.f-zz)*nn+zz*sx[r][c];
    }
    __syncthreads();
    if(w<4) ln_row(sy,szb,g2,b2ln,w,l);
    __syncthreads();
    // FFN1: rows t and t+256 of w1, each read once.
    {
        float acc0[4]={0,0,0,0}, acc1[4]={0,0,0,0};
        const float4* wa=(const float4*)(w1+(size_t)t*128);
        const float4* wb2=(const float4*)(w1+(size_t)(t+256)*128);
        for(int d=0;d<32;d++){
            float4 a=wa[d], bb=wb2[d];
#pragma unroll
            for(int r=0;r<4;r++){
                float4 zz=((const float4*)szb[r])[d];
                acc0[r]+=dot4(zz,a); acc1[r]+=dot4(zz,bb);
            }
        }
        float b0=b1[t], b256=b1[t+256];
        __syncthreads();   // szb (sh1 alias) consumed; about to overwrite
#pragma unroll
        for(int r=0;r<4;r++){
            sh1[r][t]=fmaxf(acc0[r]+b0,0.f);
            sh1[r][t+256]=fmaxf(acc1[r]+b256,0.f);
        }
    }
    __syncthreads();
    // FFN2: thread (c, K-half h over 256). w2 row c read once.
    {
        int c=t&127, h=t>>7;
        float acc[4]={0,0,0,0};
        const float4* wp=(const float4*)(w2+(size_t)c*512+h*256);
        for(int d=0;d<64;d++){
            float4 wv=wp[d];
#pragma unroll
            for(int k=0;k<4;k++) acc[k]+=dot4(((const float4*)(sh1[k]+h*256))[d],wv);
        }
#pragma unroll
        for(int k=0;k<4;k++) pu[h][k][c]=acc[k];
    }
    __syncthreads();
#pragma unroll
    for(int j=0;j<2;j++){
        int i=t+j*256, r=i>>7, c=i&127;
        float val=sy[r][c]+pu[0][r][c]+pu[1][r][c]+b2f[c];
        g_qstate[(b*16+qh+r)*128+c]=val;
        su[r][c]=val;
        if(last) qout[(b*16+qh+r)*128+c]=val;
    }
    __syncthreads();
    if(last) return;
    // next-iter qk: LN(qnew), then @M1 with K-split
    if(w<4) ln_row(su,szb,gq,bq,w,l);
    __syncthreads();
    {
        int c=t&127, h=t>>7;
        float acc[4]={0,0,0,0};
        for(int e=h*64;e<h*64+64;e++){
            float mv=g_M1[e*128+c];
#pragma unroll
            for(int k=0;k<4;k++) acc[k]=fmaf(szb[k][e],mv,acc[k]);
        }
#pragma unroll
        for(int k=0;k<4;k++) pu[h][k][c]=acc[k];
    }
    __syncthreads();
#pragma unroll
    for(int j=0;j<2;j++){
        int i=t+j*256, r=i>>7, c=i&127;
        Sh[r][c]=pu[0][r][c]+pu[1][r][c];
    }
    __syncthreads();
    if(w<4){
        int qbase=b*16+qh;
        float4 qr=((const float4*)Sh[w])[l];
        float4 g4=((const float4*)gkv)[l], b4=((const float4*)bkv)[l];
        float c1=dot4(qr,g4), c0=dot4(qr,b4);
#pragma unroll
        for(int d=16;d>0;d>>=1){c1+=__shfl_xor_sync(FULL,c1,d);c0+=__shfl_xor_sync(FULL,c0,d);}
        if(l==0){g_cq1[qbase+w]=c1; g_cq0[qbase+w]=c0;}
        float4 o; o.x=qr.x*g4.x; o.y=qr.y*g4.y; o.z=qr.z*g4.z; o.w=qr.w*g4.w;
        ((float4*)(g_qkg+(qbase+w)*128))[l]=o;
    }
}

extern "C" void kernel_launch(void* const* d_in, const int* in_sizes, int n_in,
                              void* d_out, int out_size){
    const float* inp=(const float*)d_in[0];
    const float* query=(const float*)d_in[1];
    const float* ln_kv_g=(const float*)d_in[2];
    const float* ln_kv_b=(const float*)d_in[3];
    const float* Wk=(const float*)d_in[4];
    const float* Wv=(const float*)d_in[5];
    const float* ln_q_g=(const float*)d_in[6];
    const float* ln_q_b=(const float*)d_in[7];
    const float* Wq=(const float*)d_in[8];
    const float* gru_wih=(const float*)d_in[9];
    const float* gru_whh=(const float*)d_in[10];
    const float* gru_bih=(const float*)d_in[11];
    const float* gru_bhh=(const float*)d_in[12];
    const float* ln2_g=(const float*)d_in[13];
    const float* ln2_b=(const float*)d_in[14];
    const float* ffn_w1=(const float*)d_in[15];
    const float* ffn_b1=(const float*)d_in[16];
    const float* ffn_w2=(const float*)d_in[17];
    const float* ffn_b2=(const float*)d_in[18];
    float* out=(float*)d_out;
    float* a0out=out+32*16*128;

    int smemB = SMEMF*4;
    cudaFuncSetAttribute(kstream6, cudaFuncAttributeMaxDynamicSharedMemorySize, smemB);
    kM1<<<128,128>>>(Wq,Wk);
    kcopy<<<512,128>>>(query);
    kqk0<<<64,256>>>(ln_q_g,ln_q_b,ln_kv_g,ln_kv_b);
    for(int it=0;it<3;it++){
        int last=(it==2);
        kstream6<<<dim3(8,32),256,smemB>>>(inp,a0out,last,it==0);
        ktail2<<<128,256>>>(Wv,ln_kv_g,ln_kv_b,gru_wih,gru_whh,gru_bih,gru_bhh,
                            ln2_g,ln2_b,ffn_w1,ffn_b1,ffn_w2,ffn_b2,
                            ln_q_g,ln_q_b,out,last);
    }
}

// round 11
// speedup vs baseline: 2.2426x; 1.0156x over previous
#include <cuda_runtime.h>
#include <math.h>
#define FULL 0xffffffffu

__device__ float g_M1[128*128];
__device__ float g_qstate[32*16*128];
__device__ float g_qkg[32*16*128];
__device__ float g_cq1[32*16];
__device__ float g_cq0[32*16];
__device__ float g_Tpart[32*8*16*128];
__device__ float g_t1p[32*8*16];
__device__ float g_t2p[32*8*16];
__device__ float g_rstdc[32*4096];
__device__ float g_mc[32*4096];

static __device__ __forceinline__ float dot4(float4 a, float4 b) {
    return fmaf(a.x,b.x,fmaf(a.y,b.y,fmaf(a.z,b.z,a.w*b.w)));
}
static __device__ __forceinline__ unsigned tf32r(float x){
    unsigned u; asm("cvt.rna.tf32.f32 %0, %1;" : "=r"(u) : "f"(x)); return u;
}
#define MMA1688(D,A0,A1,A2,A3,B0,B1) \
  asm volatile("mma.sync.aligned.m16n8k8.row.col.f32.tf32.tf32.f32 " \
    "{%0,%1,%2,%3},{%4,%5,%6,%7},{%8,%9},{%0,%1,%2,%3};" \
    : "+f"(D[0]),"+f"(D[1]),"+f"(D[2]),"+f"(D[3]) \
    : "r"(A0),"r"(A1),"r"(A2),"r"(A3),"r"(B0),"r"(B1))

static __device__ __forceinline__ float fexp(float x) {
    x = fmaxf(x, -87.f);
    float t = fmaf(x, 1.4426950408889634f, 12582912.f);
    int ni = __float_as_int(t) - 0x4B400000;
    float n = t - 12582912.f;
    float f = fmaf(x, 1.4426950408889634f, -n);
    float p = 1.5403530e-4f;
    p = fmaf(p,f,1.3333558e-3f); p = fmaf(p,f,9.6181291e-3f);
    p = fmaf(p,f,5.5504109e-2f); p = fmaf(p,f,2.4022651e-1f);
    p = fmaf(p,f,6.9314718e-1f); p = fmaf(p,f,1.f);
    return p * __int_as_float((ni + 127) << 23);
}

__global__ void kcopy(const float* __restrict__ s){
    int i = blockIdx.x*128+threadIdx.x; g_qstate[i]=s[i];
}
// M1 = scale*Wq^T@Wk : smem-cached Wq column + unroll for MLP
__global__ void kM1(const float* __restrict__ Wq, const float* __restrict__ Wk){
    __shared__ float wq[128];
    int e=blockIdx.x, d=threadIdx.x;
    wq[d]=Wq[d*128+e];
    __syncthreads();
    float a=0.f;
#pragma unroll 8
    for(int c=0;c<128;c++) a=fmaf(wq[c],Wk[c*128+d],a);
    g_M1[e*128+d]=a*0.08838834764831845f;
}

static __device__ __forceinline__ void ln_row(const float (*sq)[128], float (*sz)[128],
        const float* gq, const float* bq, int w, int l){
    float4 y4=((const float4*)sq[w])[l];
    float s=y4.x+y4.y+y4.z+y4.w;
    float s2=fmaf(y4.x,y4.x,fmaf(y4.y,y4.y,fmaf(y4.z,y4.z,y4.w*y4.w)));
#pragma unroll
    for(int d=16;d>0;d>>=1){s+=__shfl_xor_sync(FULL,s,d);s2+=__shfl_xor_sync(FULL,s2,d);}
    float m=s*(1.f/128.f);
    float rstd=rsqrtf(fmaf(s2,1.f/128.f,-m*m)+1e-5f);
    float4 gg=((const float4*)gq)[l], bb=((const float4*)bq)[l];
    float4 z4;
    z4.x=fmaf((y4.x-m)*rstd,gg.x,bb.x); z4.y=fmaf((y4.y-m)*rstd,gg.y,bb.y);
    z4.z=fmaf((y4.z-m)*rstd,gg.z,bb.z); z4.w=fmaf((y4.w-m)*rstd,gg.w,bb.w);
    ((float4*)sz[w])[l]=z4;
}

template<int NR>
static __device__ __forceinline__ void qkproj(const float (*sz)[128], float (*qkraw)[128],
        const float* gkv, const float* bkv, int qbase, int t, int w, int l){
    const int RG=NR/2;
    int c=t&127, rq=(t>>7)*RG;
    float acc[RG];
#pragma unroll
    for(int k=0;k<RG;k++) acc[k]=0.f;
    for(int e=0;e<128;e++){
        float mv=g_M1[e*128+c];
#pragma unroll
        for(int k=0;k<RG;k++) acc[k]=fmaf(sz[rq+k][e],mv,acc[k]);
    }
#pragma unroll
    for(int k=0;k<RG;k++) qkraw[rq+k][c]=acc[k];
    __syncthreads();
    if(w<NR){
        float4 qr=((const float4*)qkraw[w])[l];
        float4 g4=((const float4*)gkv)[l], b4=((const float4*)bkv)[l];
        float c1=dot4(qr,g4), c0=dot4(qr,b4);
#pragma unroll
        for(int d=16;d>0;d>>=1){c1+=__shfl_xor_sync(FULL,c1,d);c0+=__shfl_xor_sync(FULL,c0,d);}
        if(l==0){g_cq1[qbase+w]=c1; g_cq0[qbase+w]=c0;}
        float4 o; o.x=qr.x*g4.x; o.y=qr.y*g4.y; o.z=qr.z*g4.z; o.w=qr.w*g4.w;
        ((float4*)(g_qkg+(qbase+w)*128))[l]=o;
    }
}

__global__ void __launch_bounds__(256) kqk0(const float* __restrict__ gq,
        const float* __restrict__ bq, const float* __restrict__ gkv,
        const float* __restrict__ bkv){
    int qbase=blockIdx.x*8, t=threadIdx.x, w=t>>5, l=t&31;
    __shared__ float sq[8][128], sz[8][128], qkraw[8][128];
#pragma unroll
    for(int k=0;k<4;k++) ((float*)sq)[k*256+t]=g_qstate[qbase*128+k*256+t];
    __syncthreads();
    ln_row(sq,sz,gq,bq,w,l);
    __syncthreads();
    qkproj<8>(sz,qkraw,gkv,bkv,qbase,t,w,l);
}

// smem float offsets for kstream7
#define STG0 0
#define QKF  16384
#define WBUF 18432
#define RSTD 20608
#define MS   21120
#define SBLK 21632
#define T1S  23680
#define T2S  23696
#define CQ1S 23712
#define CQ0S 23728
#define SMEMF 23744

// ---- single-pass stream, cp.async staging ----
__global__ void __launch_bounds__(256,2) kstream7(const float* __restrict__ inp,
        float* __restrict__ a0out, int writeA0, int iter0){
    extern __shared__ float sm[];
    int p=blockIdx.x, b=blockIdx.y, t=threadIdx.x, w=t>>5, l=t&31;
    int g=l>>2, c4=l&3;
    if(t<16){
        sm[T1S+t]=0.f; sm[T2S+t]=0.f;
        sm[CQ1S+t]=g_cq1[b*16+t]; sm[CQ0S+t]=g_cq0[b*16+t];
    }
#pragma unroll
    for(int e=0;e<8;e++){
        int gi=e*256+t;
        int j=gi&1, lane=(gi>>1)&31, kn=gi>>6;
        int k=kn>>1, nt=kn&1;
        int slot=nt*8+(lane>>2), ch=k*8+(lane&3)+j*4;
        sm[QKF+gi]=__uint_as_float(tf32r(g_qkg[b*2048+slot*128+ch]));
    }
    if(!iter0){
#pragma unroll
        for(int k=0;k<2;k++){
            sm[RSTD+k*256+t]=g_rstdc[b*4096+p*512+k*256+t];
            sm[MS+k*256+t]=g_mc[b*4096+p*512+k*256+t];
        }
    }
    __syncthreads();
    int rb=w*64;
    if(iter0){
        const float4* base=(const float4*)(inp+((size_t)b*4096+p*512+rb)*128);
        for(int i=0;i<64;i++){
            float4 x=base[i*32+l];
            float s=x.x+x.y+x.z+x.w;
            float s2=fmaf(x.x,x.x,fmaf(x.y,x.y,fmaf(x.z,x.z,x.w*x.w)));
#pragma unroll
            for(int d=16;d>0;d>>=1){s+=__shfl_xor_sync(FULL,s,d);s2+=__shfl_xor_sync(FULL,s2,d);}
            float m=s*(1.f/128.f);
            float rs=rsqrtf(fmaf(s2,1.f/128.f,-m*m)+1e-5f);
            if(l==0){sm[RSTD+rb+i]=rs;sm[MS+rb+i]=m;}
        }
        __syncthreads();
#pragma unroll
        for(int k=0;k<2;k++){
            g_rstdc[b*4096+p*512+k*256+t]=sm[RSTD+k*256+t];
            g_mc[b*4096+p*512+k*256+t]=sm[MS+k*256+t];
        }
    }
    float cq1v[4], cq0v[4];
    {
        int s0=2*c4;
        cq1v[0]=sm[CQ1S+s0];   cq1v[1]=sm[CQ1S+s0+1];
        cq1v[2]=sm[CQ1S+s0+8]; cq1v[3]=sm[CQ1S+s0+9];
        cq0v[0]=sm[CQ0S+s0];   cq0v[1]=sm[CQ0S+s0+1];
        cq0v[2]=sm[CQ0S+s0+8]; cq0v[3]=sm[CQ0S+s0+9];
    }
    float sacc[64];
#pragma unroll
    for(int i=0;i<64;i++) sacc[i]=0.f;
    float t1p[4]={0,0,0,0}, t2p[4]={0,0,0,0};
    int wst=STG0+w*2048;
    int wb=WBUF+w*272;

    for(int tile=0;tile<4;tile++){
        __syncwarp();
        int rb16=rb+tile*16;
        const float4* gsrc=(const float4*)(inp+((size_t)b*4096+p*512+rb16)*128);
        // stage 16x128 tile via cp.async (raw fp32 bits; tf32 HW truncation)
#pragma unroll
        for(int half=0;half<2;half++){
#pragma unroll
            for(int ii=0;ii<8;ii++){
                int row=ii*2+(l>>4);
                const float4* src=gsrc+row*32+half*16+(l&15);
                unsigned dst=(unsigned)__cvta_generic_to_shared(
                    sm+wst+half*1024+row*64+(((l&15)*4)^((row&7)<<2)));
                asm volatile("cp.async.ca.shared.global [%0], [%1], 16;\n"
                             ::"r"(dst),"l"(src):"memory");
            }
        }
        asm volatile("cp.async.commit_group;\n":::"memory");
        asm volatile("cp.async.wait_group 0;\n":::"memory");
        __syncwarp();
        // phase 1: logits MMA (M=row, N=slot)
        float d0[4]={0,0,0,0}, d1[4]={0,0,0,0};
        int abase=wst+g*64;
#pragma unroll
        for(int k=0;k<16;k++){
            int half=k>>3, kk=k&7;
            int ab=abase+half*1024;
            int x0=((kk*8)+c4)^(g<<2);
            unsigned a0=__float_as_uint(sm[ab+x0]);
            unsigned a1=__float_as_uint(sm[ab+512+x0]);
            unsigned a2=__float_as_uint(sm[ab+(x0^4)]);
            unsigned a3=__float_as_uint(sm[ab+512+(x0^4)]);
            float2 bb=*(const float2*)&sm[QKF+(k*2+0)*64+l*2];
            MMA1688(d0,a0,a1,a2,a3,__float_as_uint(bb.x),__float_as_uint(bb.y));
            float2 bc=*(const float2*)&sm[QKF+(k*2+1)*64+l*2];
            MMA1688(d1,a0,a1,a2,a3,__float_as_uint(bc.x),__float_as_uint(bc.y));
        }
        int r0g=rb16+g, r1g=r0g+8;
        float rs0=sm[RSTD+r0g], m0=sm[MS+r0g];
        float rs1=sm[RSTD+r1g], m1=sm[MS+r1g];
        float Lg[4], Lh[4];
        Lg[0]=fmaf(rs0,fmaf(-m0,cq1v[0],d0[0]),cq0v[0]);
        Lg[1]=fmaf(rs0,fmaf(-m0,cq1v[1],d0[1]),cq0v[1]);
        Lg[2]=fmaf(rs0,fmaf(-m0,cq1v[2],d1[0]),cq0v[2]);
        Lg[3]=fmaf(rs0,fmaf(-m0,cq1v[3],d1[1]),cq0v[3]);
        Lh[0]=fmaf(rs1,fmaf(-m1,cq1v[0],d0[2]),cq0v[0]);
        Lh[1]=fmaf(rs1,fmaf(-m1,cq1v[1],d0[3]),cq0v[1]);
        Lh[2]=fmaf(rs1,fmaf(-m1,cq1v[2],d1[2]),cq0v[2]);
        Lh[3]=fmaf(rs1,fmaf(-m1,cq1v[3],d1[3]),cq0v[3]);
        float mx0=fmaxf(fmaxf(Lg[0],Lg[1]),fmaxf(Lg[2],Lg[3]));
        float mx1=fmaxf(fmaxf(Lh[0],Lh[1]),fmaxf(Lh[2],Lh[3]));
        mx0=fmaxf(mx0,__shfl_xor_sync(FULL,mx0,1));
        mx0=fmaxf(mx0,__shfl_xor_sync(FULL,mx0,2));
        mx1=fmaxf(mx1,__shfl_xor_sync(FULL,mx1,1));
        mx1=fmaxf(mx1,__shfl_xor_sync(FULL,mx1,2));
        float ag[4], ah[4], sum0=0.f, sum1=0.f;
#pragma unroll
        for(int j=0;j<4;j++){
            ag[j]=fexp(Lg[j]-mx0); sum0+=ag[j];
            ah[j]=fexp(Lh[j]-mx1); sum1+=ah[j];
        }
        sum0+=__shfl_xor_sync(FULL,sum0,1); sum0+=__shfl_xor_sync(FULL,sum0,2);
        sum1+=__shfl_xor_sync(FULL,sum1,1); sum1+=__shfl_xor_sync(FULL,sum1,2);
        float inv0=1.f/sum0, inv1=1.f/sum1;
        float rm0=rs0*m0, rm1=rs1*m1;
#pragma unroll
        for(int j=0;j<4;j++){
            ag[j]*=inv0; ah[j]*=inv1;
            t2p[j]+=ag[j]+ah[j];
            t1p[j]+=ag[j]*rm0+ah[j]*rm1;
        }
        {
            int s0=2*c4;
            sm[wb+g*17+s0]=ag[0];     sm[wb+g*17+s0+1]=ag[1];
            sm[wb+g*17+s0+8]=ag[2];   sm[wb+g*17+s0+9]=ag[3];
            sm[wb+(g+8)*17+s0]=ah[0]; sm[wb+(g+8)*17+s0+1]=ah[1];
            sm[wb+(g+8)*17+s0+8]=ah[2]; sm[wb+(g+8)*17+s0+9]=ah[3];
        }
        __syncwarp();
        if(writeA0){
            int row=l&15, sh=l>>4;
#pragma unroll
            for(int j=0;j<8;j++){
                int slot=j*2+sh;
                a0out[(size_t)b*65536+(size_t)slot*4096+p*512+rb16+row]=sm[wb+row*17+slot];
            }
        }
        // phase 3: S += w^T @ x  (M=slot, K=row, N=ch)
#pragma unroll
        for(int kc=0;kc<2;kc++){
            int ra=kc*8+c4, rb2=ra+4;
            float rsa=sm[RSTD+rb16+ra], rsb=sm[RSTD+rb16+rb2];
            unsigned A0=tf32r(sm[wb+ra*17+g]*rsa);
            unsigned A1=tf32r(sm[wb+ra*17+g+8]*rsa);
            unsigned A2=tf32r(sm[wb+rb2*17+g]*rsb);
            unsigned A3=tf32r(sm[wb+rb2*17+g+8]*rsb);
            int swa=(c4<<2), swb=((c4+4)<<2);
#pragma unroll
            for(int nt=0;nt<16;nt++){
                int half=nt>>3;
                int chh=(nt&7)*8+g;
                int c16=chh>>2, frac=chh&3;
                unsigned B0=__float_as_uint(sm[wst+half*1024+ra*64+(((c16*4)^swa)+frac)]);
                unsigned B1=__float_as_uint(sm[wst+half*1024+rb2*64+(((c16*4)^swb)+frac)]);
                MMA1688((&sacc[nt*4]),A0,A1,A2,A3,B0,B1);
            }
        }
    }
#pragma unroll
    for(int j=0;j<4;j++){
#pragma unroll
        for(int d=4;d<32;d<<=1){
            t2p[j]+=__shfl_xor_sync(FULL,t2p[j],d);
            t1p[j]+=__shfl_xor_sync(FULL,t1p[j],d);
        }
    }
    if(l<4){
        int s0=2*l;
        atomicAdd(&sm[T2S+s0],t2p[0]);   atomicAdd(&sm[T2S+s0+1],t2p[1]);
        atomicAdd(&sm[T2S+s0+8],t2p[2]); atomicAdd(&sm[T2S+s0+9],t2p[3]);
        atomicAdd(&sm[T1S+s0],t1p[0]);   atomicAdd(&sm[T1S+s0+1],t1p[1]);
        atomicAdd(&sm[T1S+s0+8],t1p[2]); atomicAdd(&sm[T1S+s0+9],t1p[3]);
    }
    __syncthreads();
    for(int i=t;i<2048;i+=256) sm[SBLK+i]=0.f;
    __syncthreads();
#pragma unroll
    for(int nt=0;nt<16;nt++){
        int ch0=nt*8+2*c4;
        atomicAdd(&sm[SBLK+g*128+ch0],sacc[nt*4+0]);
        atomicAdd(&sm[SBLK+g*128+ch0+1],sacc[nt*4+1]);
        atomicAdd(&sm[SBLK+(g+8)*128+ch0],sacc[nt*4+2]);
        atomicAdd(&sm[SBLK+(g+8)*128+ch0+1],sacc[nt*4+3]);
    }
    __syncthreads();
    float* tp=g_Tpart+((size_t)(b*8+p))*2048;
    for(int i=t;i<2048;i+=256) tp[i]=sm[SBLK+i];
    if(t<16){g_t1p[(b*8+p)*16+t]=sm[T1S+t];g_t2p[(b*8+p)*16+t]=sm[T2S+t];}
}

// ---- ktail v2 (unchanged R10) ----
__global__ void __launch_bounds__(256) ktail2(const float* __restrict__ Wv,
        const float* __restrict__ gkv, const float* __restrict__ bkv,
        const float* __restrict__ wih, const float* __restrict__ whh,
        const float* __restrict__ bih, const float* __restrict__ bhh,
        const float* __restrict__ g2, const float* __restrict__ b2ln,
        const float* __restrict__ w1, const float* __restrict__ b1,
        const float* __restrict__ w2, const float* __restrict__ b2f,
        const float* __restrict__ gq, const float* __restrict__ bq,
        float* __restrict__ qout, int last){
    int blk=blockIdx.x, b=blk>>2, qh=(blk&3)*4;
    int t=threadIdx.x, w=t>>5, l=t&31;
    __shared__ float Sh[4][128], su[4][128], sx[4][128], sy[4][128];
    __shared__ float gg[4][772];
    __shared__ float pu[2][4][128];
    __shared__ float sh1[4][512];
    __shared__ float t1a[4], t2a[4], rsa[4];
    float (*szb)[128] = (float(*)[128])sh1;

    if(t<4){
        float s1=0.f,s2=0.f;
        for(int p=0;p<8;p++){
            s1+=g_t1p[(b*8+p)*16+qh+t];
            s2+=g_t2p[(b*8+p)*16+qh+t];
        }
        t1a[t]=s1; t2a[t]=s2; rsa[t]=1.f/(s2+1e-5f);
    }
#pragma unroll
    for(int k=0;k<2;k++)
        ((float*)sx)[k*256+t]=g_qstate[(b*16+qh)*128+k*256+t];
    __syncthreads();
#pragma unroll
    for(int k=0;k<2;k++){
        int idx=k*256+t, q=idx>>7, c=idx&127;
        float a=0.f;
        for(int p=0;p<8;p++) a+=g_Tpart[((size_t)(b*8+p))*2048+(qh+q)*128+c];
        ((float*)Sh)[idx]=fmaf(gkv[c],a-t1a[q],bkv[c]*t2a[q]);
    }
    __syncthreads();
    {
        int c=t&127, h=t>>7;
        float acc[4]={0,0,0,0};
        const float4* wr=(const float4*)(Wv+(size_t)c*128+h*64);
        for(int d=0;d<16;d++){
            float4 wv=wr[d];
#pragma unroll
            for(int k=0;k<4;k++) acc[k]+=dot4(((const float4*)(Sh[k]+h*64))[d],wv);
        }
#pragma unroll
        for(int k=0;k<4;k++) pu[h][k][c]=acc[k];
    }
    __syncthreads();
#pragma unroll
    for(int j=0;j<2;j++){
        int i=t+j*256, r=i>>7, c=i&127;
        su[r][c]=(pu[0][r][c]+pu[1][r][c])*rsa[r];
    }
    __syncthreads();
#pragma unroll
    for(int j=0;j<3;j++){
        int o=t+j*256;
        const float* wrow = (o<384) ? (wih+(size_t)o*128) : (whh+(size_t)(o-384)*128);
        const float (*A)[128] = (o<384) ? su : sx;
        const float4* wr=(const float4*)wrow;
        float acc[4]={0,0,0,0};
        for(int d=0;d<32;d++){
            float4 wv=wr[d];
#pragma unroll
            for(int k=0;k<4;k++) acc[k]+=dot4(((const float4*)A[k])[d],wv);
        }
#pragma unroll
        for(int k=0;k<4;k++) gg[k][o]=acc[k];
    }
    __syncthreads();
#pragma unroll
    for(int j=0;j<2;j++){
        int i=t+j*256, r=i>>7, c=i&127;
        float rr=1.f/(1.f+fexp(-(gg[r][c]+bih[c]+gg[r][384+c]+bhh[c])));
        float zz=1.f/(1.f+fexp(-(gg[r][128+c]+bih[128+c]+gg[r][512+c]+bhh[128+c])));
        float nn=tanhf(gg[r][256+c]+bih[256+c]+rr*(gg[r][640+c]+bhh[256+c]));
        sy[r][c]=(1.f-zz)*nn+zz*sx[r][c];
    }
    __syncthreads();
    if(w<4) ln_row(sy,szb,g2,b2ln,w,l);
    __syncthreads();
    {
        float acc0[4]={0,0,0,0}, acc1[4]={0,0,0,0};
        const float4* wa=(const float4*)(w1+(size_t)t*128);
        const float4* wb2=(const float4*)(w1+(size_t)(t+256)*128);
        for(int d=0;d<32;d++){
            float4 a=wa[d], bb=wb2[d];
#pragma unroll
            for(int r=0;r<4;r++){
                float4 zz=((const float4*)szb[r])[d];
                acc0[r]+=dot4(zz,a); acc1[r]+=dot4(zz,bb);
            }
        }
        float b0=b1[t], b256=b1[t+256];
        __syncthreads();
#pragma unroll
        for(int r=0;r<4;r++){
            sh1[r][t]=fmaxf(acc0[r]+b0,0.f);
            sh1[r][t+256]=fmaxf(acc1[r]+b256,0.f);
        }
    }
    __syncthreads();
    {
        int c=t&127, h=t>>7;
        float acc[4]={0,0,0,0};
        const float4* wp=(const float4*)(w2+(size_t)c*512+h*256);
        for(int d=0;d<64;d++){
            float4 wv=wp[d];
#pragma unroll
            for(int k=0;k<4;k++) acc[k]+=dot4(((const float4*)(sh1[k]+h*256))[d],wv);
        }
#pragma unroll
        for(int k=0;k<4;k++) pu[h][k][c]=acc[k];
    }
    __syncthreads();
#pragma unroll
    for(int j=0;j<2;j++){
        int i=t+j*256, r=i>>7, c=i&127;
        float val=sy[r][c]+pu[0][r][c]+pu[1][r][c]+b2f[c];
        g_qstate[(b*16+qh+r)*128+c]=val;
        su[r][c]=val;
        if(last) qout[(b*16+qh+r)*128+c]=val;
    }
    __syncthreads();
    if(last) return;
    if(w<4) ln_row(su,szb,gq,bq,w,l);
    __syncthreads();
    {
        int c=t&127, h=t>>7;
        float acc[4]={0,0,0,0};
        for(int e=h*64;e<h*64+64;e++){
            float mv=g_M1[e*128+c];
#pragma unroll
            for(int k=0;k<4;k++) acc[k]=fmaf(szb[k][e],mv,acc[k]);
        }
#pragma unroll
        for(int k=0;k<4;k++) pu[h][k][c]=acc[k];
    }
    __syncthreads();
#pragma unroll
    for(int j=0;j<2;j++){
        int i=t+j*256, r=i>>7, c=i&127;
        Sh[r][c]=pu[0][r][c]+pu[1][r][c];
    }
    __syncthreads();
    if(w<4){
        int qbase=b*16+qh;
        float4 qr=((const float4*)Sh[w])[l];
        float4 g4=((const float4*)gkv)[l], b4=((const float4*)bkv)[l];
        float c1=dot4(qr,g4), c0=dot4(qr,b4);
#pragma unroll
        for(int d=16;d>0;d>>=1){c1+=__shfl_xor_sync(FULL,c1,d);c0+=__shfl_xor_sync(FULL,c0,d);}
        if(l==0){g_cq1[qbase+w]=c1; g_cq0[qbase+w]=c0;}
        float4 o; o.x=qr.x*g4.x; o.y=qr.y*g4.y; o.z=qr.z*g4.z; o.w=qr.w*g4.w;
        ((float4*)(g_qkg+(qbase+w)*128))[l]=o;
    }
}

extern "C" void kernel_launch(void* const* d_in, const int* in_sizes, int n_in,
                              void* d_out, int out_size){
    const float* inp=(const float*)d_in[0];
    const float* query=(const float*)d_in[1];
    const float* ln_kv_g=(const float*)d_in[2];
    const float* ln_kv_b=(const float*)d_in[3];
    const float* Wk=(const float*)d_in[4];
    const float* Wv=(const float*)d_in[5];
    const float* ln_q_g=(const float*)d_in[6];
    const float* ln_q_b=(const float*)d_in[7];
    const float* Wq=(const float*)d_in[8];
    const float* gru_wih=(const float*)d_in[9];
    const float* gru_whh=(const float*)d_in[10];
    const float* gru_bih=(const float*)d_in[11];
    const float* gru_bhh=(const float*)d_in[12];
    const float* ln2_g=(const float*)d_in[13];
    const float* ln2_b=(const float*)d_in[14];
    const float* ffn_w1=(const float*)d_in[15];
    const float* ffn_b1=(const float*)d_in[16];
    const float* ffn_w2=(const float*)d_in[17];
    const float* ffn_b2=(const float*)d_in[18];
    float* out=(float*)d_out;
    float* a0out=out+32*16*128;

    int smemB = SMEMF*4;
    cudaFuncSetAttribute(kstream7, cudaFuncAttributeMaxDynamicSharedMemorySize, smemB);
    kM1<<<128,128>>>(Wq,Wk);
    kcopy<<<512,128>>>(query);
    kqk0<<<64,256>>>(ln_q_g,ln_q_b,ln_kv_g,ln_kv_b);
    for(int it=0;it<3;it++){
        int last=(it==2);
        kstream7<<<dim3(8,32),256,smemB>>>(inp,a0out,last,it==0);
        ktail2<<<128,256>>>(Wv,ln_kv_g,ln_kv_b,gru_wih,gru_whh,gru_bih,gru_bhh,
                            ln2_g,ln2_b,ffn_w1,ffn_b1,ffn_w2,ffn_b2,
                            ln_q_g,ln_q_b,out,last);
    }
}

// round 13
// speedup vs baseline: 2.3111x; 1.0305x over previous
#include <cuda_runtime.h>
#include <math.h>
#define FULL 0xffffffffu

__device__ float g_M1[128*128];
__device__ float g_qstate[32*16*128];
__device__ float g_qkg[32*16*128];
__device__ float g_cq1[32*16];
__device__ float g_cq0[32*16];
__device__ float g_Tpart[32*8*16*128];
__device__ float g_t1p[32*8*16];
__device__ float g_t2p[32*8*16];
__device__ float g_rstdc[32*4096];
__device__ float g_mc[32*4096];

static __device__ __forceinline__ float dot4(float4 a, float4 b) {
    return fmaf(a.x,b.x,fmaf(a.y,b.y,fmaf(a.z,b.z,a.w*b.w)));
}
static __device__ __forceinline__ unsigned tf32r(float x){
    unsigned u; asm("cvt.rna.tf32.f32 %0, %1;" : "=r"(u) : "f"(x)); return u;
}
#define MMA1688(D,A0,A1,A2,A3,B0,B1) \
  asm volatile("mma.sync.aligned.m16n8k8.row.col.f32.tf32.tf32.f32 " \
    "{%0,%1,%2,%3},{%4,%5,%6,%7},{%8,%9},{%0,%1,%2,%3};" \
    : "+f"(D[0]),"+f"(D[1]),"+f"(D[2]),"+f"(D[3]) \
    : "r"(A0),"r"(A1),"r"(A2),"r"(A3),"r"(B0),"r"(B1))

static __device__ __forceinline__ float fexp(float x) {
    x = fmaxf(x, -87.f);
    float t = fmaf(x, 1.4426950408889634f, 12582912.f);
    int ni = __float_as_int(t) - 0x4B400000;
    float n = t - 12582912.f;
    float f = fmaf(x, 1.4426950408889634f, -n);
    float p = 1.5403530e-4f;
    p = fmaf(p,f,1.3333558e-3f); p = fmaf(p,f,9.6181291e-3f);
    p = fmaf(p,f,5.5504109e-2f); p = fmaf(p,f,2.4022651e-1f);
    p = fmaf(p,f,6.9314718e-1f); p = fmaf(p,f,1.f);
    return p * __int_as_float((ni + 127) << 23);
}

__global__ void kM1(const float* __restrict__ Wq, const float* __restrict__ Wk){
    __shared__ float wq[128];
    int e=blockIdx.x, d=threadIdx.x;
    wq[d]=Wq[d*128+e];
    __syncthreads();
    float a=0.f;
#pragma unroll 8
    for(int c=0;c<128;c++) a=fmaf(wq[c],Wk[c*128+d],a);
    g_M1[e*128+d]=a*0.08838834764831845f;
}

static __device__ __forceinline__ void ln_row(const float (*sq)[128], float (*sz)[128],
        const float* gq, const float* bq, int w, int l){
    float4 y4=((const float4*)sq[w])[l];
    float s=y4.x+y4.y+y4.z+y4.w;
    float s2=fmaf(y4.x,y4.x,fmaf(y4.y,y4.y,fmaf(y4.z,y4.z,y4.w*y4.w)));
#pragma unroll
    for(int d=16;d>0;d>>=1){s+=__shfl_xor_sync(FULL,s,d);s2+=__shfl_xor_sync(FULL,s2,d);}
    float m=s*(1.f/128.f);
    float rstd=rsqrtf(fmaf(s2,1.f/128.f,-m*m)+1e-5f);
    float4 gg=((const float4*)gq)[l], bb=((const float4*)bq)[l];
    float4 z4;
    z4.x=fmaf((y4.x-m)*rstd,gg.x,bb.x); z4.y=fmaf((y4.y-m)*rstd,gg.y,bb.y);
    z4.z=fmaf((y4.z-m)*rstd,gg.z,bb.z); z4.w=fmaf((y4.w-m)*rstd,gg.w,bb.w);
    ((float4*)sz[w])[l]=z4;
}

template<int NR>
static __device__ __forceinline__ void qkproj(const float (*sz)[128], float (*qkraw)[128],
        const float* gkv, const float* bkv, int qbase, int t, int w, int l){
    const int RG=NR/2;
    int c=t&127, rq=(t>>7)*RG;
    float acc[RG];
#pragma unroll
    for(int k=0;k<RG;k++) acc[k]=0.f;
    for(int e=0;e<128;e++){
        float mv=g_M1[e*128+c];
#pragma unroll
        for(int k=0;k<RG;k++) acc[k]=fmaf(sz[rq+k][e],mv,acc[k]);
    }
#pragma unroll
    for(int k=0;k<RG;k++) qkraw[rq+k][c]=acc[k];
    __syncthreads();
    if(w<NR){
        float4 qr=((const float4*)qkraw[w])[l];
        float4 g4=((const float4*)gkv)[l], b4=((const float4*)bkv)[l];
        float c1=dot4(qr,g4), c0=dot4(qr,b4);
#pragma unroll
        for(int d=16;d>0;d>>=1){c1+=__shfl_xor_sync(FULL,c1,d);c0+=__shfl_xor_sync(FULL,c0,d);}
        if(l==0){g_cq1[qbase+w]=c1; g_cq0[qbase+w]=c0;}
        float4 o; o.x=qr.x*g4.x; o.y=qr.y*g4.y; o.z=qr.z*g4.z; o.w=qr.w*g4.w;
        ((float4*)(g_qkg+(qbase+w)*128))[l]=o;
    }
}

// init: copy query -> qstate AND compute first qkg/cq
__global__ void __launch_bounds__(256) kqk0(const float* __restrict__ query,
        const float* __restrict__ gq,
        const float* __restrict__ bq, const float* __restrict__ gkv,
        const float* __restrict__ bkv){
    int qbase=blockIdx.x*8, t=threadIdx.x, w=t>>5, l=t&31;
    __shared__ float sq[8][128], sz[8][128], qkraw[8][128];
#pragma unroll
    for(int k=0;k<4;k++){
        float v=query[qbase*128+k*256+t];
        ((float*)sq)[k*256+t]=v;
        g_qstate[qbase*128+k*256+t]=v;
    }
    __syncthreads();
    ln_row(sq,sz,gq,bq,w,l);
    __syncthreads();
    qkproj<8>(sz,qkraw,gkv,bkv,qbase,t,w,l);
}

// smem float offsets
#define STG0 0
#define QKF  16384
#define WBUF 18432
#define RSTD 20608
#define MS   21120
#define SBLK 21632
#define T1S  23680
#define T2S  23696
#define CQ1S 23712
#define CQ0S 23728
#define SMEMF 23744

// ---- single-pass stream: cp.async.cg staging, LDS.128 B-loads ----
__global__ void __launch_bounds__(256,2) kstream9(const float* __restrict__ inp,
        float* __restrict__ a0out, int writeA0, int iter0){
    extern __shared__ float sm[];
    int p=blockIdx.x, b=blockIdx.y, t=threadIdx.x, w=t>>5, l=t&31;
    int g=l>>2, c4=l&3;
    if(t<16){
        sm[T1S+t]=0.f; sm[T2S+t]=0.f;
        sm[CQ1S+t]=g_cq1[b*16+t]; sm[CQ0S+t]=g_cq0[b*16+t];
    }
    // B fragments, interleaved: [k][lane][nt0j0, nt0j1, nt1j0, nt1j1]
#pragma unroll
    for(int e=0;e<8;e++){
        int gi=e*256+t;
        int j=gi&1, nt=(gi>>1)&1, lane=(gi>>2)&31, k=gi>>7;
        int slot=nt*8+(lane>>2), ch=k*8+(lane&3)+j*4;
        sm[QKF+gi]=__uint_as_float(tf32r(g_qkg[b*2048+slot*128+ch]));
    }
    if(!iter0){
#pragma unroll
        for(int k=0;k<2;k++){
            sm[RSTD+k*256+t]=g_rstdc[b*4096+p*512+k*256+t];
            sm[MS+k*256+t]=g_mc[b*4096+p*512+k*256+t];
        }
    }
    __syncthreads();
    int rb=w*64;
    if(iter0){
        const float4* base=(const float4*)(inp+((size_t)b*4096+p*512+rb)*128);
        for(int i=0;i<64;i++){
            float4 x=base[i*32+l];
            float s=x.x+x.y+x.z+x.w;
            float s2=fmaf(x.x,x.x,fmaf(x.y,x.y,fmaf(x.z,x.z,x.w*x.w)));
#pragma unroll
            for(int d=16;d>0;d>>=1){s+=__shfl_xor_sync(FULL,s,d);s2+=__shfl_xor_sync(FULL,s2,d);}
            float m=s*(1.f/128.f);
            float rs=rsqrtf(fmaf(s2,1.f/128.f,-m*m)+1e-5f);
            if(l==0){sm[RSTD+rb+i]=rs;sm[MS+rb+i]=m;}
        }
        __syncthreads();
#pragma unroll
        for(int k=0;k<2;k++){
            g_rstdc[b*4096+p*512+k*256+t]=sm[RSTD+k*256+t];
            g_mc[b*4096+p*512+k*256+t]=sm[MS+k*256+t];
        }
    }
    float cq1v[4], cq0v[4];
    {
        int s0=2*c4;
        cq1v[0]=sm[CQ1S+s0];   cq1v[1]=sm[CQ1S+s0+1];
        cq1v[2]=sm[CQ1S+s0+8]; cq1v[3]=sm[CQ1S+s0+9];
        cq0v[0]=sm[CQ0S+s0];   cq0v[1]=sm[CQ0S+s0+1];
        cq0v[2]=sm[CQ0S+s0+8]; cq0v[3]=sm[CQ0S+s0+9];
    }
    float sacc[64];
#pragma unroll
    for(int i=0;i<64;i++) sacc[i]=0.f;
    float t1p[4]={0,0,0,0}, t2p[4]={0,0,0,0};
    int wst=STG0+w*2048;
    int wb=WBUF+w*272;

    for(int tile=0;tile<4;tile++){
        __syncwarp();
        int rb16=rb+tile*16;
        const float4* gsrc=(const float4*)(inp+((size_t)b*4096+p*512+rb16)*128);
        // stage 16x128 tile via cp.async.cg (L1 bypass)
#pragma unroll
        for(int half=0;half<2;half++){
#pragma unroll
            for(int ii=0;ii<8;ii++){
                int row=ii*2+(l>>4);
                const float4* src=gsrc+row*32+half*16+(l&15);
                unsigned dst=(unsigned)__cvta_generic_to_shared(
                    sm+wst+half*1024+row*64+(((l&15)*4)^((row&7)<<2)));
                asm volatile("cp.async.cg.shared.global [%0], [%1], 16;\n"
                             ::"r"(dst),"l"(src):"memory");
            }
        }
        asm volatile("cp.async.commit_group;\n":::"memory");
        asm volatile("cp.async.wait_group 0;\n":::"memory");
        __syncwarp();
        // phase 1: logits MMA (M=row, N=slot), B via one LDS.128 per k
        float d0[4]={0,0,0,0}, d1[4]={0,0,0,0};
        int abase=wst+g*64;
#pragma unroll
        for(int k=0;k<16;k++){
            int half=k>>3, kk=k&7;
            int ab=abase+half*1024;
            int x0=((kk*8)+c4)^(g<<2);
            unsigned a0=__float_as_uint(sm[ab+x0]);
            unsigned a1=__float_as_uint(sm[ab+512+x0]);
            unsigned a2=__float_as_uint(sm[ab+(x0^4)]);
            unsigned a3=__float_as_uint(sm[ab+512+(x0^4)]);
            float4 bv=*(const float4*)&sm[QKF+k*128+l*4];
            MMA1688(d0,a0,a1,a2,a3,__float_as_uint(bv.x),__float_as_uint(bv.y));
            MMA1688(d1,a0,a1,a2,a3,__float_as_uint(bv.z),__float_as_uint(bv.w));
        }
        int r0g=rb16+g, r1g=r0g+8;
        float rs0=sm[RSTD+r0g], m0=sm[MS+r0g];
        float rs1=sm[RSTD+r1g], m1=sm[MS+r1g];
        float Lg[4], Lh[4];
        Lg[0]=fmaf(rs0,fmaf(-m0,cq1v[0],d0[0]),cq0v[0]);
        Lg[1]=fmaf(rs0,fmaf(-m0,cq1v[1],d0[1]),cq0v[1]);
        Lg[2]=fmaf(rs0,fmaf(-m0,cq1v[2],d1[0]),cq0v[2]);
        Lg[3]=fmaf(rs0,fmaf(-m0,cq1v[3],d1[1]),cq0v[3]);
        Lh[0]=fmaf(rs1,fmaf(-m1,cq1v[0],d0[2]),cq0v[0]);
        Lh[1]=fmaf(rs1,fmaf(-m1,cq1v[1],d0[3]),cq0v[1]);
        Lh[2]=fmaf(rs1,fmaf(-m1,cq1v[2],d1[2]),cq0v[2]);
        Lh[3]=fmaf(rs1,fmaf(-m1,cq1v[3],d1[3]),cq0v[3]);
        float mx0=fmaxf(fmaxf(Lg[0],Lg[1]),fmaxf(Lg[2],Lg[3]));
        float mx1=fmaxf(fmaxf(Lh[0],Lh[1]),fmaxf(Lh[2],Lh[3]));
        mx0=fmaxf(mx0,__shfl_xor_sync(FULL,mx0,1));
        mx0=fmaxf(mx0,__shfl_xor_sync(FULL,mx0,2));
        mx1=fmaxf(mx1,__shfl_xor_sync(FULL,mx1,1));
        mx1=fmaxf(mx1,__shfl_xor_sync(FULL,mx1,2));
        float ag[4], ah[4], sum0=0.f, sum1=0.f;
#pragma unroll
        for(int j=0;j<4;j++){
            ag[j]=fexp(Lg[j]-mx0); sum0+=ag[j];
            ah[j]=fexp(Lh[j]-mx1); sum1+=ah[j];
        }
        sum0+=__shfl_xor_sync(FULL,sum0,1); sum0+=__shfl_xor_sync(FULL,sum0,2);
        sum1+=__shfl_xor_sync(FULL,sum1,1); sum1+=__shfl_xor_sync(FULL,sum1,2);
        float inv0=1.f/sum0, inv1=1.f/sum1;
        float rm0=rs0*m0, rm1=rs1*m1;
#pragma unroll
        for(int j=0;j<4;j++){
            ag[j]*=inv0; ah[j]*=inv1;
            t2p[j]+=ag[j]+ah[j];
            t1p[j]+=ag[j]*rm0+ah[j]*rm1;
        }
        {
            int s0=2*c4;
            sm[wb+g*17+s0]=ag[0];     sm[wb+g*17+s0+1]=ag[1];
            sm[wb+g*17+s0+8]=ag[2];   sm[wb+g*17+s0+9]=ag[3];
            sm[wb+(g+8)*17+s0]=ah[0]; sm[wb+(g+8)*17+s0+1]=ah[1];
            sm[wb+(g+8)*17+s0+8]=ah[2]; sm[wb+(g+8)*17+s0+9]=ah[3];
        }
        __syncwarp();
        if(writeA0){
            int row=l&15, sh=l>>4;
#pragma unroll
            for(int j=0;j<8;j++){
                int slot=j*2+sh;
                a0out[(size_t)b*65536+(size_t)slot*4096+p*512+rb16+row]=sm[wb+row*17+slot];
            }
        }
        // phase 3: S += w^T @ x  (M=slot, K=row, N=ch)
#pragma unroll
        for(int kc=0;kc<2;kc++){
            int ra=kc*8+c4, rb2=ra+4;
            float rsa=sm[RSTD+rb16+ra], rsb=sm[RSTD+rb16+rb2];
            unsigned A0=tf32r(sm[wb+ra*17+g]*rsa);
            unsigned A1=tf32r(sm[wb+ra*17+g+8]*rsa);
            unsigned A2=tf32r(sm[wb+rb2*17+g]*rsb);
            unsigned A3=tf32r(sm[wb+rb2*17+g+8]*rsb);
            int swa=(c4<<2), swb=((c4+4)<<2);
#pragma unroll
            for(int nt=0;nt<16;nt++){
                int half=nt>>3;
                int chh=(nt&7)*8+g;
                int c16=chh>>2, frac=chh&3;
                unsigned B0=__float_as_uint(sm[wst+half*1024+ra*64+(((c16*4)^swa)+frac)]);
                unsigned B1=__float_as_uint(sm[wst+half*1024+rb2*64+(((c16*4)^swb)+frac)]);
                MMA1688((&sacc[nt*4]),A0,A1,A2,A3,B0,B1);
            }
        }
    }
#pragma unroll
    for(int j=0;j<4;j++){
#pragma unroll
        for(int d=4;d<32;d<<=1){
            t2p[j]+=__shfl_xor_sync(FULL,t2p[j],d);
            t1p[j]+=__shfl_xor_sync(FULL,t1p[j],d);
        }
    }
    if(l<4){
        int s0=2*l;
        atomicAdd(&sm[T2S+s0],t2p[0]);   atomicAdd(&sm[T2S+s0+1],t2p[1]);
        atomicAdd(&sm[T2S+s0+8],t2p[2]); atomicAdd(&sm[T2S+s0+9],t2p[3]);
        atomicAdd(&sm[T1S+s0],t1p[0]);   atomicAdd(&sm[T1S+s0+1],t1p[1]);
        atomicAdd(&sm[T1S+s0+8],t1p[2]); atomicAdd(&sm[T1S+s0+9],t1p[3]);
    }
    __syncthreads();
    for(int i=t;i<2048;i+=256) sm[SBLK+i]=0.f;
    __syncthreads();
#pragma unroll
    for(int nt=0;nt<16;nt++){
        int ch0=nt*8+2*c4;
        atomicAdd(&sm[SBLK+g*128+ch0],sacc[nt*4+0]);
        atomicAdd(&sm[SBLK+g*128+ch0+1],sacc[nt*4+1]);
        atomicAdd(&sm[SBLK+(g+8)*128+ch0],sacc[nt*4+2]);
        atomicAdd(&sm[SBLK+(g+8)*128+ch0+1],sacc[nt*4+3]);
    }
    __syncthreads();
    float* tp=g_Tpart+((size_t)(b*8+p))*2048;
    for(int i=t;i<2048;i+=256) tp[i]=sm[SBLK+i];
    if(t<16){g_t1p[(b*8+p)*16+t]=sm[T1S+t];g_t2p[(b*8+p)*16+t]=sm[T2S+t];}
}

// ---- ktail v2 (unchanged) ----
__global__ void __launch_bounds__(256) ktail2(const float* __restrict__ Wv,
        const float* __restrict__ gkv, const float* __restrict__ bkv,
        const float* __restrict__ wih, const float* __restrict__ whh,
        const float* __restrict__ bih, const float* __restrict__ bhh,
        const float* __restrict__ g2, const float* __restrict__ b2ln,
        const float* __restrict__ w1, const float* __restrict__ b1,
        const float* __restrict__ w2, const float* __restrict__ b2f,
        const float* __restrict__ gq, const float* __restrict__ bq,
        float* __restrict__ qout, int last){
    int blk=blockIdx.x, b=blk>>2, qh=(blk&3)*4;
    int t=threadIdx.x, w=t>>5, l=t&31;
    __shared__ float Sh[4][128], su[4][128], sx[4][128], sy[4][128];
    __shared__ float gg[4][772];
    __shared__ float pu[2][4][128];
    __shared__ float sh1[4][512];
    __shared__ float t1a[4], t2a[4], rsa[4];
    float (*szb)[128] = (float(*)[128])sh1;

    if(t<4){
        float s1=0.f,s2=0.f;
        for(int p=0;p<8;p++){
            s1+=g_t1p[(b*8+p)*16+qh+t];
            s2+=g_t2p[(b*8+p)*16+qh+t];
        }
        t1a[t]=s1; t2a[t]=s2; rsa[t]=1.f/(s2+1e-5f);
    }
#pragma unroll
    for(int k=0;k<2;k++)
        ((float*)sx)[k*256+t]=g_qstate[(b*16+qh)*128+k*256+t];
    __syncthreads();
#pragma unroll
    for(int k=0;k<2;k++){
        int idx=k*256+t, q=idx>>7, c=idx&127;
        float a=0.f;
        for(int p=0;p<8;p++) a+=g_Tpart[((size_t)(b*8+p))*2048+(qh+q)*128+c];
        ((float*)Sh)[idx]=fmaf(gkv[c],a-t1a[q],bkv[c]*t2a[q]);
    }
    __syncthreads();
    {
        int c=t&127, h=t>>7;
        float acc[4]={0,0,0,0};
        const float4* wr=(const float4*)(Wv+(size_t)c*128+h*64);
        for(int d=0;d<16;d++){
            float4 wv=wr[d];
#pragma unroll
            for(int k=0;k<4;k++) acc[k]+=dot4(((const float4*)(Sh[k]+h*64))[d],wv);
        }
#pragma unroll
        for(int k=0;k<4;k++) pu[h][k][c]=acc[k];
    }
    __syncthreads();
#pragma unroll
    for(int j=0;j<2;j++){
        int i=t+j*256, r=i>>7, c=i&127;
        su[r][c]=(pu[0][r][c]+pu[1][r][c])*rsa[r];
    }
    __syncthreads();
#pragma unroll
    for(int j=0;j<3;j++){
        int o=t+j*256;
        const float* wrow = (o<384) ? (wih+(size_t)o*128) : (whh+(size_t)(o-384)*128);
        const float (*A)[128] = (o<384) ? su : sx;
        const float4* wr=(const float4*)wrow;
        float acc[4]={0,0,0,0};
        for(int d=0;d<32;d++){
            float4 wv=wr[d];
#pragma unroll
            for(int k=0;k<4;k++) acc[k]+=dot4(((const float4*)A[k])[d],wv);
        }
#pragma unroll
        for(int k=0;k<4;k++) gg[k][o]=acc[k];
    }
    __syncthreads();
#pragma unroll
    for(int j=0;j<2;j++){
        int i=t+j*256, r=i>>7, c=i&127;
        float rr=1.f/(1.f+fexp(-(gg[r][c]+bih[c]+gg[r][384+c]+bhh[c])));
        float zz=1.f/(1.f+fexp(-(gg[r][128+c]+bih[128+c]+gg[r][512+c]+bhh[128+c])));
        float nn=tanhf(gg[r][256+c]+bih[256+c]+rr*(gg[r][640+c]+bhh[256+c]));
        sy[r][c]=(1.f-zz)*nn+zz*sx[r][c];
    }
    __syncthreads();
    if(w<4) ln_row(sy,szb,g2,b2ln,w,l);
    __syncthreads();
    {
        float acc0[4]={0,0,0,0}, acc1[4]={0,0,0,0};
        const float4* wa=(const float4*)(w1+(size_t)t*128);
        const float4* wb2=(const float4*)(w1+(size_t)(t+256)*128);
        for(int d=0;d<32;d++){
            float4 a=wa[d], bb=wb2[d];
#pragma unroll
            for(int r=0;r<4;r++){
                float4 zz=((const float4*)szb[r])[d];
                acc0[r]+=dot4(zz,a); acc1[r]+=dot4(zz,bb);
            }
        }
        float b0=b1[t], b256=b1[t+256];
        __syncthreads();
#pragma unroll
        for(int r=0;r<4;r++){
            sh1[r][t]=fmaxf(acc0[r]+b0,0.f);
            sh1[r][t+256]=fmaxf(acc1[r]+b256,0.f);
        }
    }
    __syncthreads();
    {
        int c=t&127, h=t>>7;
        float acc[4]={0,0,0,0};
        const float4* wp=(const float4*)(w2+(size_t)c*512+h*256);
        for(int d=0;d<64;d++){
            float4 wv=wp[d];
#pragma unroll
            for(int k=0;k<4;k++) acc[k]+=dot4(((const float4*)(sh1[k]+h*256))[d],wv);
        }
#pragma unroll
        for(int k=0;k<4;k++) pu[h][k][c]=acc[k];
    }
    __syncthreads();
#pragma unroll
    for(int j=0;j<2;j++){
        int i=t+j*256, r=i>>7, c=i&127;
        float val=sy[r][c]+pu[0][r][c]+pu[1][r][c]+b2f[c];
        g_qstate[(b*16+qh+r)*128+c]=val;
        su[r][c]=val;
        if(last) qout[(b*16+qh+r)*128+c]=val;
    }
    __syncthreads();
    if(last) return;
    if(w<4) ln_row(su,szb,gq,bq,w,l);
    __syncthreads();
    {
        int c=t&127, h=t>>7;
        float acc[4]={0,0,0,0};
        for(int e=h*64;e<h*64+64;e++){
            float mv=g_M1[e*128+c];
#pragma unroll
            for(int k=0;k<4;k++) acc[k]=fmaf(szb[k][e],mv,acc[k]);
        }
#pragma unroll
        for(int k=0;k<4;k++) pu[h][k][c]=acc[k];
    }
    __syncthreads();
#pragma unroll
    for(int j=0;j<2;j++){
        int i=t+j*256, r=i>>7, c=i&127;
        Sh[r][c]=pu[0][r][c]+pu[1][r][c];
    }
    __syncthreads();
    if(w<4){
        int qbase=b*16+qh;
        float4 qr=((const float4*)Sh[w])[l];
        float4 g4=((const float4*)gkv)[l], b4=((const float4*)bkv)[l];
        float c1=dot4(qr,g4), c0=dot4(qr,b4);
#pragma unroll
        for(int d=16;d>0;d>>=1){c1+=__shfl_xor_sync(FULL,c1,d);c0+=__shfl_xor_sync(FULL,c0,d);}
        if(l==0){g_cq1[qbase+w]=c1; g_cq0[qbase+w]=c0;}
        float4 o; o.x=qr.x*g4.x; o.y=qr.y*g4.y; o.z=qr.z*g4.z; o.w=qr.w*g4.w;
        ((float4*)(g_qkg+(qbase+w)*128))[l]=o;
    }
}

extern "C" void kernel_launch(void* const* d_in, const int* in_sizes, int n_in,
                              void* d_out, int out_size){
    const float* inp=(const float*)d_in[0];
    const float* query=(const float*)d_in[1];
    const float* ln_kv_g=(const float*)d_in[2];
    const float* ln_kv_b=(const float*)d_in[3];
    const float* Wk=(const float*)d_in[4];
    const float* Wv=(const float*)d_in[5];
    const float* ln_q_g=(const float*)d_in[6];
    const float* ln_q_b=(const float*)d_in[7];
    const float* Wq=(const float*)d_in[8];
    const float* gru_wih=(const float*)d_in[9];
    const float* gru_whh=(const float*)d_in[10];
    const float* gru_bih=(const float*)d_in[11];
    const float* gru_bhh=(const float*)d_in[12];
    const float* ln2_g=(const float*)d_in[13];
    const float* ln2_b=(const float*)d_in[14];
    const float* ffn_w1=(const float*)d_in[15];
    const float* ffn_b1=(const float*)d_in[16];
    const float* ffn_w2=(const float*)d_in[17];
    const float* ffn_b2=(const float*)d_in[18];
    float* out=(float*)d_out;
    float* a0out=out+32*16*128;

    int smemB = SMEMF*4;
    cudaFuncSetAttribute(kstream9, cudaFuncAttributeMaxDynamicSharedMemorySize, smemB);
    kM1<<<128,128>>>(Wq,Wk);
    kqk0<<<64,256>>>(query,ln_q_g,ln_q_b,ln_kv_g,ln_kv_b);
    for(int it=0;it<3;it++){
        int last=(it==2);
        kstream9<<<dim3(8,32),256,smemB>>>(inp,a0out,last,it==0);
        ktail2<<<128,256>>>(Wv,ln_kv_g,ln_kv_b,gru_wih,gru_whh,gru_bih,gru_bhh,
                            ln2_g,ln2_b,ffn_w1,ffn_b1,ffn_w2,ffn_b2,
                            ln_q_g,ln_q_b,out,last);
    }
}